// round 4
// baseline (speedup 1.0000x reference)
#include <cuda_runtime.h>
#include <cuda_bf16.h>

#define BB   256
#define T0   1000
#define T1C  1001
#define C1   22
#define C2   25
#define NEP  3
#define NU   (BB*NEP)   // 768
#define MM   30
#define TW   128

// ---------------- scratch ----------------
__device__ float g_y1  [BB*C1*T0];
__device__ float g_sig [BB*C2*T1C];
__device__ float g_cov [NU*625];
__device__ float g_V   [NU*MM*625];
__device__ float g_p   [NU*MM];
__device__ float g_xm  [NU*625];
__device__ float g_logQ2[BB*3*324];
__device__ float g_logK2[BB*3*324];
__device__ float g_logV2[BB*3*324];
__device__ float g_feat [BB*513];

__device__ __forceinline__ float warp_sum(float v){
    #pragma unroll
    for (int o=16;o;o>>=1) v += __shfl_xor_sync(0xffffffffu, v, o);
    return v;
}

__device__ __forceinline__ void patch_info(int i, int&k, int&pr, int&pc, int&gi){
    if (i<16){ gi=0;k=2;pr=i/4;pc=i%4; }
    else if (i<25){ gi=1;k=3;int p=i-16;pr=p/3;pc=p%3; }
    else if (i<29){ gi=2;k=4;int p=i-25;pr=p/2;pc=p%2; }
    else { gi=3;k=5;pr=0;pc=0; }
}

// ---------------- per-warp Jacobi workspace ----------------
struct WS {
    float A[625];
    float V[625];
    float c[16];
    float s[16];
    int   p[16];
    int   q[16];
};

// Parallel-ordering (round-robin tournament) two-sided Jacobi.
// A: n*n symmetric in shared. On return eigenvalues on diag(A), vectors in columns of V.
__device__ void warp_pjacobi(WS& w, int n){
    int lane=threadIdx.x&31;
    float* A=w.A; float* Vv=w.V;
    for (int e=lane;e<n*n;e+=32) Vv[e]=((e%(n+1))==0)?1.f:0.f;
    float nrm2=0.f;
    for (int e=lane;e<n*n;e+=32) nrm2+=A[e]*A[e];
    nrm2=warp_sum(nrm2);
    float stop =nrm2*1e-14f+1e-32f;   // sweep stop: off-diag Fro^2
    float tiny =nrm2*1e-28f+1e-38f;   // per-rotation skip
    int m=(n+1)&~1, P=m>>1, R=m-1;
    int total=P*n;
    int iters=(total+31)>>5;
    __syncwarp();
    for (int sweep=0;sweep<15;sweep++){
        float off2=0.f;
        for (int e=lane;e<n*n;e+=32){ int r=e/n,c2=e-r*n; if(r!=c2) off2+=A[e]*A[e]; }
        off2=warp_sum(off2);
        if (off2<=stop) break;
        for (int r=0;r<R;r++){
            if (lane<P){
                int i=lane, j=m-1-lane;
                int a=(i==0)?0:(1+(r+i-1)%(m-1));
                int b=1+(r+j-1)%(m-1);
                int p=min(a,b), q=max(a,b);
                float c0=1.f,s0=0.f;
                if (q<n){
                    float apq=A[p*n+q];
                    if (apq*apq>tiny){
                        float app=A[p*n+p], aqq=A[q*n+q];
                        float tau=(aqq-app)/(2.f*apq);
                        float t=copysignf(1.f,tau)/(fabsf(tau)+sqrtf(1.f+tau*tau));
                        c0=rsqrtf(1.f+t*t); s0=t*c0;
                    }
                }
                w.p[lane]=p; w.q[lane]=q; w.c[lane]=c0; w.s[lane]=s0;
            }
            __syncwarp();
            // column rotations (A*J) fused with V*J
            for (int it=0;it<iters;it++){
                int idx=it*32+lane;
                if (idx<total){
                    int pr=idx/n, k=idx-pr*n;
                    int p=w.p[pr], q=w.q[pr];
                    if (q<n){
                        float c0=w.c[pr], s0=w.s[pr];
                        float akp=A[k*n+p], akq=A[k*n+q];
                        A[k*n+p]=c0*akp-s0*akq; A[k*n+q]=s0*akp+c0*akq;
                        float vkp=Vv[k*n+p], vkq=Vv[k*n+q];
                        Vv[k*n+p]=c0*vkp-s0*vkq; Vv[k*n+q]=s0*vkp+c0*vkq;
                    }
                }
            }
            __syncwarp();
            // row rotations (J^T * (A*J))
            for (int it=0;it<iters;it++){
                int idx=it*32+lane;
                if (idx<total){
                    int pr=idx/n, k=idx-pr*n;
                    int p=w.p[pr], q=w.q[pr];
                    if (q<n){
                        float c0=w.c[pr], s0=w.s[pr];
                        float apk=A[p*n+k], aqk=A[q*n+k];
                        A[p*n+k]=c0*apk-s0*aqk; A[q*n+k]=s0*apk+c0*aqk;
                    }
                }
            }
            __syncwarp();
        }
    }
    __syncwarp();
}

// ---------------- per-thread 4x4 eigh -> matrix log ----------------
__device__ __forceinline__ void eigh4_log(const float* m, float* out){
    float a[16], v[16];
    #pragma unroll
    for (int i=0;i<16;i++){ a[i]=m[i]; v[i]=((i%5)==0)?1.f:0.f; }
    float nrm=0.f;
    #pragma unroll
    for (int i=0;i<16;i++) nrm+=a[i]*a[i];
    float thr=nrm*1e-15f+1e-38f;
    for (int sw=0;sw<10;sw++){
        bool rot=false;
        #pragma unroll
        for (int p=0;p<3;p++){
            #pragma unroll
            for (int q=p+1;q<4;q++){
                float apq=a[p*4+q];
                if (apq*apq>thr){
                    rot=true;
                    float app=a[p*5], aqq=a[q*5];
                    float tau=(aqq-app)/(2.f*apq);
                    float t=copysignf(1.f,tau)/(fabsf(tau)+sqrtf(1.f+tau*tau));
                    float c=rsqrtf(1.f+t*t), s=t*c;
                    #pragma unroll
                    for (int k2=0;k2<4;k2++){
                        float akp=a[k2*4+p], akq=a[k2*4+q];
                        a[k2*4+p]=c*akp-s*akq; a[k2*4+q]=s*akp+c*akq;
                        float vkp=v[k2*4+p], vkq=v[k2*4+q];
                        v[k2*4+p]=c*vkp-s*vkq; v[k2*4+q]=s*vkp+c*vkq;
                    }
                    #pragma unroll
                    for (int k2=0;k2<4;k2++){
                        float apk=a[p*4+k2], aqk=a[q*4+k2];
                        a[p*4+k2]=c*apk-s*aqk; a[q*4+k2]=s*apk+c*aqk;
                    }
                }
            }
        }
        if (!rot) break;
    }
    float fw[4];
    #pragma unroll
    for (int i=0;i<4;i++) fw[i]=logf(fmaxf(a[i*5],1e-9f));
    #pragma unroll
    for (int i=0;i<16;i++){
        int r2=i/4, c2=i%4;
        float acc=0.f;
        #pragma unroll
        for (int k2=0;k2<4;k2++) acc+=v[r2*4+k2]*fw[k2]*v[c2*4+k2];
        out[i]=acc;
    }
}

// ---------------- conv1 + bn1 ----------------
__global__ void k_conv1(const float* __restrict__ x, const float* __restrict__ w,
                        const float* __restrict__ cb, const float* __restrict__ bg,
                        const float* __restrict__ bb, const float* __restrict__ bm,
                        const float* __restrict__ bv){
    __shared__ float sw[C1*C1];
    __shared__ float ssc[C1], ssh[C1];
    int tid=threadIdx.x;
    for (int i=tid;i<C1*C1;i+=blockDim.x) sw[i]=w[i];
    if (tid<C1){
        float sc=bg[tid]*rsqrtf(bv[tid]+1e-5f);
        ssc[tid]=sc; ssh[tid]=bb[tid]+(cb[tid]-bm[tid])*sc;
    }
    __syncthreads();
    int b=blockIdx.y; int t=blockIdx.x*blockDim.x+tid;
    if (t>=T0) return;
    float xv[C1];
    #pragma unroll
    for (int h=0;h<C1;h++) xv[h]=x[(b*C1+h)*T0+t];
    #pragma unroll 1
    for (int o=0;o<C1;o++){
        float acc=0.f;
        #pragma unroll
        for (int h=0;h<C1;h++) acc+=xv[h]*sw[o*C1+h];
        g_y1[(b*C1+o)*T0+t]=acc*ssc[o]+ssh[o];
    }
}

// ---------------- conv2 (12-tap, pad 6/6) + bn2 ----------------
__global__ void k_conv2(const float* __restrict__ w2, const float* __restrict__ cb,
                        const float* __restrict__ bg, const float* __restrict__ bb,
                        const float* __restrict__ bm, const float* __restrict__ bv){
    __shared__ float sw[C2*C1*12];
    __shared__ float sy[C1*(TW+12)];
    __shared__ float ssc[C2], ssh[C2];
    int tid=threadIdx.x;
    for (int i=tid;i<C2*C1*12;i+=TW) sw[i]=w2[i];
    if (tid<C2){
        float sc=bg[tid]*rsqrtf(bv[tid]+1e-5f);
        ssc[tid]=sc; ssh[tid]=bb[tid]+(cb[tid]-bm[tid])*sc;
    }
    int b=blockIdx.y; int t0=blockIdx.x*TW;
    for (int i=tid;i<C1*(TW+12);i+=TW){
        int c=i/(TW+12), u=i%(TW+12);
        int tt=t0-6+u;
        sy[i]=(tt>=0 && tt<T0)? g_y1[(b*C1+c)*T0+tt] : 0.f;
    }
    __syncthreads();
    int t=t0+tid;
    if (t>=T1C) return;
    float acc[C2];
    #pragma unroll
    for (int o=0;o<C2;o++) acc[o]=0.f;
    for (int c=0;c<C1;c++){
        float yv[12];
        #pragma unroll
        for (int kk=0;kk<12;kk++) yv[kk]=sy[c*(TW+12)+tid+kk];
        #pragma unroll 1
        for (int o=0;o<C2;o++){
            float a=acc[o];
            #pragma unroll
            for (int kk=0;kk<12;kk++) a+=yv[kk]*sw[(o*C1+c)*12+kk];
            acc[o]=a;
        }
    }
    #pragma unroll 1
    for (int o=0;o<C2;o++) g_sig[(b*C2+o)*T1C+t]=acc[o]*ssc[o]+ssh[o];
}

// ---------------- per (b,epoch) covariance ----------------
__global__ void k_cov(){
    __shared__ float s[C2*334];
    __shared__ float cc[325];
    __shared__ float tr_s;
    int u=blockIdx.x, b=u/NEP, e=u%NEP;
    int off=e*334; int L=(e==2)?333:334;
    int tid=threadIdx.x;
    for (int idx=tid; idx<C2*L; idx+=256){
        int c=idx/L, t=idx%L;
        s[c*334+t]=g_sig[(b*C2+c)*T1C+off+t];
    }
    __syncthreads();
    if (tid<C2){
        float acc=0.f;
        for (int t=0;t<L;t++) acc+=s[tid*334+t];
        float mean=acc/(float)L;
        for (int t=0;t<L;t++) s[tid*334+t]-=mean;
    }
    __syncthreads();
    for (int r=tid;r<325;r+=256){
        int i=0, rr=r;
        while (rr>=C2-i){ rr-=C2-i; i++; }
        int j=i+rr;
        float acc=0.f;
        for (int t=0;t<L;t++) acc+=s[i*334+t]*s[j*334+t];
        cc[r]=acc/(float)(L-1);
    }
    __syncthreads();
    if (tid==0){
        float tr=0.f;
        for (int i=0;i<C2;i++) tr+=cc[i*C2 - i*(i-1)/2];
        tr_s=tr;
    }
    __syncthreads();
    float inv=1.f/tr_s;
    float* dst=g_cov+u*625;
    for (int e2=tid;e2<625;e2+=256){
        int i=e2/25, j=e2%25;
        int ii=min(i,j), jj=max(i,j);
        float v=cc[ii*C2 - ii*(ii-1)/2 + (jj-ii)]*inv;
        if (i==j) v+=1e-5f;
        dst[e2]=v;
    }
}

// ---------------- K_i (30) + Q_29 logs, score softmax -> g_p (4 units/block) ----
__global__ void k_qk(const float* __restrict__ sk0,const float* __restrict__ sk1,
                     const float* __restrict__ sk2,const float* __restrict__ sk3,
                     const float* __restrict__ sq3){
    __shared__ float scov[4][625];
    __shared__ float sK[4][31*16];
    int warp=threadIdx.x>>5, lane=threadIdx.x&31;
    int u=blockIdx.x*4+warp;
    const float* cov=g_cov+u*625;
    for (int e=lane;e<625;e+=32) scov[warp][e]=cov[e];
    __syncwarp();
    if (lane<31){
        int i=(lane==30)?29:lane;
        int k,pr,pc,gi; patch_info(i,k,pr,pc,gi);
        int kk=k*k;
        const float* W=(lane==30)? sq3 : (gi==0?sk0:gi==1?sk1:gi==2?sk2:sk3);
        float Km[16];
        #pragma unroll
        for (int e=0;e<16;e++) Km[e]=0.f;
        for (int c=0;c<kk;c++){
            int ic=(pr+c/k)*5 + pc + c%k;
            float sa[4]={0.f,0.f,0.f,0.f};
            for (int r=0;r<kk;r++){
                int ir=(pr+r/k)*5 + pc + r%k;
                float xx=scov[warp][ir*25+ic];
                #pragma unroll
                for (int a=0;a<4;a++) sa[a]+=W[r*4+a]*xx;
            }
            #pragma unroll
            for (int a=0;a<4;a++)
                #pragma unroll
                for (int b2=0;b2<4;b2++) Km[a*4+b2]+=sa[a]*W[c*4+b2];
        }
        #pragma unroll
        for (int d=0;d<4;d++) Km[d*5]+=2.5e-5f*(1.f+d);
        float logm[16];
        eigh4_log(Km, logm);
        #pragma unroll
        for (int e=0;e<16;e++) sK[warp][lane*16+e]=logm[e];
    }
    __syncwarp();
    float scval=-1e30f;
    if (lane<30){
        float kn=0.f,cr=0.f,qn=0.f;
        #pragma unroll
        for (int e=0;e<16;e++){
            float a=sK[warp][lane*16+e], q=sK[warp][30*16+e];
            kn+=a*a; cr+=a*q; qn+=q*q;
        }
        float E=fmaxf(kn+qn-2.f*cr,0.f);
        scval=1.f/(1.f+log1pf(E));
    }
    float mx=scval;
    #pragma unroll
    for (int o=16;o;o>>=1) mx=fmaxf(mx,__shfl_xor_sync(0xffffffffu,mx,o));
    float ev=(lane<30)?expf(scval-mx):0.f;
    float sm=warp_sum(ev);
    if (lane<30) g_p[u*30+lane]=ev/sm;
}

// ---------------- logV_i (25x25 per warp) ----------------
__global__ void k_logV(const float* __restrict__ sv0,const float* __restrict__ sv1,
                       const float* __restrict__ sv2,const float* __restrict__ sv3){
    __shared__ WS ws[8];
    int warp=threadIdx.x>>5, lane=threadIdx.x&31;
    int gw=blockIdx.x*8+warp;
    if (gw>=NU*MM) return;
    int u=gw/MM, i=gw%MM;
    WS& w=ws[warp];
    int k,pr,pc,gi; patch_info(i,k,pr,pc,gi);
    int kk=k*k;
    const float* sv=(gi==0?sv0:gi==1?sv1:gi==2?sv2:sv3);
    const float* cov=g_cov+u*625;
    // sub (kk x kk) into w.A
    for (int e=lane;e<kk*kk;e+=32){
        int r=e/kk, c=e%kk;
        int ir=(pr+r/k)*5+pc+r%k;
        int ic=(pr+c/k)*5+pc+c%k;
        w.A[e]=cov[ir*25+ic];
    }
    __syncwarp();
    // T = sub @ W  (kk x 25) into w.V
    for (int e=lane;e<kk*25;e+=32){
        int r=e/25, b=e%25;
        float acc=0.f;
        for (int c=0;c<kk;c++) acc+=w.A[r*kk+c]*sv[c*25+b];
        w.V[e]=acc;
    }
    __syncwarp();
    // A = W^T T + jitter  (25 x 25)
    for (int e=lane;e<625;e+=32){
        int a=e/25, b=e%25;
        float acc=0.f;
        for (int r=0;r<kk;r++) acc+=sv[r*25+a]*w.V[r*25+b];
        if (a==b) acc+=4e-6f*(1.f+a);
        w.A[e]=acc;
    }
    __syncwarp();
    warp_pjacobi(w,25);
    if (lane<25){ float d=w.A[lane*26]; w.A[lane*26]=logf(fmaxf(d,1e-9f)); }
    __syncwarp();
    float* out=g_V+(size_t)gw*625;
    for (int e=lane;e<625;e+=32){
        int a=e/25, b=e%25;
        float acc=0.f;
        for (int kx=0;kx<25;kx++) acc+=w.V[a*25+kx]*w.A[kx*26]*w.V[b*25+kx];
        out[e]=acc;
    }
}

// ---------------- out_log = sum p_i logV_i ; xm = rect(exp(.)) ----------------
__global__ void k_att1(){
    __shared__ WS ws[8];
    __shared__ float pp[8][30];
    int warp=threadIdx.x>>5, lane=threadIdx.x&31;
    int u=blockIdx.x*8+warp;
    if (u>=NU) return;
    WS& w=ws[warp];
    if (lane<30) pp[warp][lane]=g_p[u*30+lane];
    __syncwarp();
    const float* Vb=g_V+(size_t)u*30*625;
    for (int e=lane;e<625;e+=32){
        float acc=0.f;
        #pragma unroll 5
        for (int i=0;i<30;i++) acc+=pp[warp][i]*Vb[(size_t)i*625+e];
        w.A[e]=acc;
    }
    __syncwarp();
    warp_pjacobi(w,25);
    if (lane<25) w.A[lane*26]=fmaxf(expf(w.A[lane*26]),1e-4f);
    __syncwarp();
    float* dst=g_xm+u*625;
    for (int e=lane;e<625;e+=32){
        int a=e/25, b=e%25;
        float acc=0.f;
        for (int kx=0;kx<25;kx++) acc+=w.V[a*25+kx]*w.A[kx*26]*w.V[b*25+kx];
        dst[e]=acc;
    }
}

// ---------------- stage-2 logs: log(W^T xm W), 18x18 ----------------
__global__ void k_s2log(const float* __restrict__ mq,const float* __restrict__ mk,
                        const float* __restrict__ mv){
    __shared__ WS ws[8];
    int warp=threadIdx.x>>5, lane=threadIdx.x&31;
    int id=blockIdx.x*8+warp;
    if (id>=BB*9) return;
    int b=id/9, rem=id%9, t=rem/3, c=rem%3;
    WS& w=ws[warp];
    const float* W=(c==0?mq:(c==1?mk:mv));
    const float* X=g_xm+(b*3+t)*625;
    for (int e=lane;e<450;e+=32){
        int r=e/18, a=e%18;
        float acc=0.f;
        for (int cc=0;cc<25;cc++) acc+=X[r*25+cc]*W[cc*18+a];
        w.V[e]=acc;
    }
    __syncwarp();
    for (int e=lane;e<324;e+=32){
        int a=e/18, bb=e%18;
        float acc=0.f;
        for (int r=0;r<25;r++) acc+=W[r*18+a]*w.V[r*18+bb];
        w.A[e]=acc;
    }
    __syncwarp();
    warp_pjacobi(w,18);
    if (lane<18) w.A[lane*19]=logf(fmaxf(w.A[lane*19],1e-9f));
    __syncwarp();
    float* dst=(c==0?g_logQ2:(c==1?g_logK2:g_logV2))+(b*3+t)*324;
    for (int e=lane;e<324;e+=32){
        int a=e/18, bb=e%18;
        float acc=0.f;
        for (int kx=0;kx<18;kx++) acc+=w.V[a*18+kx]*w.A[kx*19]*w.V[bb*18+kx];
        dst[e]=acc;
    }
}

// ---------------- stage-2 attention + fused rect/log -> feat ----------------
__global__ void k_s2att(){
    __shared__ WS ws[8];
    int warp=threadIdx.x>>5, lane=threadIdx.x&31;
    int id=blockIdx.x*8+warp;
    if (id>=BB*3) return;
    int b=id/3, j=id%3;
    WS& w=ws[warp];
    const float* lQ=g_logQ2+(b*3+j)*324;
    float qn=0.f;
    for (int e=lane;e<324;e+=32){ float v=lQ[e]; qn+=v*v; }
    qn=warp_sum(qn);
    float p3[3];
    #pragma unroll
    for (int i=0;i<3;i++){
        const float* lK=g_logK2+(b*3+i)*324;
        float kn=0.f, cr=0.f;
        for (int e=lane;e<324;e+=32){ float a=lK[e], q=lQ[e]; kn+=a*a; cr+=a*q; }
        kn=warp_sum(kn); cr=warp_sum(cr);
        float E=fmaxf(kn+qn-2.f*cr,0.f);
        p3[i]=1.f/(1.f+log1pf(E));
    }
    float mx=fmaxf(p3[0],fmaxf(p3[1],p3[2]));
    float sm=0.f;
    #pragma unroll
    for (int i=0;i<3;i++){ p3[i]=expf(p3[i]-mx); sm+=p3[i]; }
    #pragma unroll
    for (int i=0;i<3;i++) p3[i]/=sm;
    for (int e=lane;e<324;e+=32){
        float acc=0.f;
        #pragma unroll
        for (int i=0;i<3;i++) acc+=p3[i]*g_logV2[(b*3+i)*324+e];
        w.A[e]=acc;
    }
    __syncwarp();
    warp_pjacobi(w,18);
    if (lane<18) w.A[lane*19]=fmaxf(w.A[lane*19], -9.210340371976184f);
    __syncwarp();
    for (int r=lane;r<171;r+=32){
        int ii=0, rr=r;
        while (rr>=18-ii){ rr-=18-ii; ii++; }
        int jj=ii+rr;
        float acc=0.f;
        for (int kx=0;kx<18;kx++) acc+=w.V[ii*18+kx]*w.A[kx*19]*w.V[jj*18+kx];
        float coef=(ii==jj)?1.f:1.41421356237309515f;
        g_feat[b*513 + j*171 + r]=acc*coef;
    }
}

// ---------------- linear head ----------------
__global__ void k_head(const float* __restrict__ lw, const float* __restrict__ lb,
                       float* __restrict__ out){
    int b=blockIdx.x; int o=threadIdx.x>>5; int lane=threadIdx.x&31;
    if (o>=4) return;
    float acc=0.f;
    for (int r=lane;r<513;r+=32) acc+=g_feat[b*513+r]*lw[o*513+r];
    acc=warp_sum(acc);
    if (lane==0) out[b*4+o]=acc+lb[o];
}

extern "C" void kernel_launch(void* const* d_in, const int* in_sizes, int n_in,
                              void* d_out, int out_size){
    const float* x   =(const float*)d_in[0];
    const float* c1w =(const float*)d_in[1];
    const float* c1b =(const float*)d_in[2];
    const float* bn1g=(const float*)d_in[3];
    const float* bn1b=(const float*)d_in[4];
    const float* bn1m=(const float*)d_in[5];
    const float* bn1v=(const float*)d_in[6];
    const float* c2w =(const float*)d_in[7];
    const float* c2b =(const float*)d_in[8];
    const float* bn2g=(const float*)d_in[9];
    const float* bn2b=(const float*)d_in[10];
    const float* bn2m=(const float*)d_in[11];
    const float* bn2v=(const float*)d_in[12];
    bool inter = (in_sizes[14]==16);
    const float *sk[4], *sv[4], *sq3p;
    if (inter){
        sq3p=(const float*)d_in[13+3*3];
        for (int g=0; g<4; g++){
            sk[g]=(const float*)d_in[14+3*g];
            sv[g]=(const float*)d_in[15+3*g];
        }
    } else {
        sq3p=(const float*)d_in[16];
        for (int g=0; g<4; g++){
            sk[g]=(const float*)d_in[17+g];
            sv[g]=(const float*)d_in[21+g];
        }
    }
    const float* mq=(const float*)d_in[25];
    const float* mk=(const float*)d_in[26];
    const float* mv=(const float*)d_in[27];
    const float* lw=(const float*)d_in[28];
    const float* lb=(const float*)d_in[29];

    k_conv1<<<dim3(8,BB),128>>>(x,c1w,c1b,bn1g,bn1b,bn1m,bn1v);
    k_conv2<<<dim3(8,BB),128>>>(c2w,c2b,bn2g,bn2b,bn2m,bn2v);
    k_cov  <<<NU,256>>>();
    k_qk   <<<NU/4,128>>>(sk[0],sk[1],sk[2],sk[3],sq3p);
    k_logV <<<(NU*MM)/8,256>>>(sv[0],sv[1],sv[2],sv[3]);
    k_att1 <<<NU/8,256>>>();
    k_s2log<<<(BB*9)/8,256>>>(mq,mk,mv);
    k_s2att<<<(BB*3)/8,256>>>();
    k_head <<<BB,128>>>(lw,lb,(float*)d_out);
}

// round 5
// speedup vs baseline: 1.9246x; 1.9246x over previous
#include <cuda_runtime.h>
#include <cuda_bf16.h>

#define BB   256
#define T0   1000
#define T1C  1001
#define C1   22
#define C2   25
#define NEP  3
#define NU   (BB*NEP)
#define MM   30
#define TW   128
#define WJ   6

__device__ float g_y1  [BB*C1*T0];
__device__ float g_sig [BB*C2*T1C];
__device__ float g_cov [NU*625];
__device__ float g_V   [NU*MM*625];
__device__ float g_p   [NU*MM];
__device__ float g_xm  [NU*625];
__device__ float g_logQ2[BB*3*324];
__device__ float g_logK2[BB*3*324];
__device__ float g_logV2[BB*3*324];
__device__ float g_feat [BB*513];

__device__ __forceinline__ float warp_sum(float v){
    #pragma unroll
    for (int o=16;o;o>>=1) v += __shfl_xor_sync(0xffffffffu, v, o);
    return v;
}

__device__ __forceinline__ void patch_info(int i, int&k, int&pr, int&pc, int&gi){
    if (i<16){ gi=0;k=2;pr=i/4;pc=i%4; }
    else if (i<25){ gi=1;k=3;int p=i-16;pr=p/3;pc=p%3; }
    else if (i<29){ gi=2;k=4;int p=i-25;pr=p/2;pc=p%2; }
    else { gi=3;k=5;pr=0;pc=0; }
}

__device__ void pairs_init(int* pairs, int n){
    if (threadIdx.x==0){
        int c=0;
        for(int p=0;p<n-1;p++) for(int q=p+1;q<n;q++) pairs[c++]=(p<<8)|q;
    }
    __syncthreads();
}

// Cyclic Jacobi with per-sweep ballot-compacted worklist.
__device__ void warp_jacobi(float* A, float* Vv, int n, const int* pairs, int np, int* wl){
    int lane=threadIdx.x&31;
    for (int e=lane;e<n*n;e+=32) Vv[e]=((e%(n+1))==0)?1.f:0.f;
    float nrm=0.f;
    for (int e=lane;e<n*n;e+=32) nrm+=A[e]*A[e];
    nrm=warp_sum(nrm);
    float thr=nrm*1e-15f+1e-38f;
    __syncwarp();
    for (int sweep=0;sweep<20;sweep++){
        int cnt=0;
        for (int base=0;base<np;base+=32){
            int idx=base+lane; bool act=false; int pq=0;
            if (idx<np){
                pq=pairs[idx];
                float a=A[(pq>>8)*n+(pq&255)];
                act=(a*a>thr);
            }
            unsigned m=__ballot_sync(0xffffffffu,act);
            if (act) wl[cnt+__popc(m&((1u<<lane)-1u))]=pq;
            cnt+=__popc(m);
        }
        if (!cnt) break;
        __syncwarp();
        for (int i=0;i<cnt;i++){
            int pq=wl[i];
            int p=pq>>8, q=pq&255;
            float apq=A[p*n+q];
            if (apq*apq>thr){
                float app=A[p*n+p], aqq=A[q*n+q];
                float tau=(aqq-app)/(2.f*apq);
                float t=copysignf(1.f,tau)/(fabsf(tau)+sqrtf(1.f+tau*tau));
                float c=rsqrtf(1.f+t*t), s=t*c;
                __syncwarp();
                if (lane<n){
                    float akp=A[lane*n+p], akq=A[lane*n+q];
                    A[lane*n+p]=c*akp-s*akq; A[lane*n+q]=s*akp+c*akq;
                    float vkp=Vv[lane*n+p], vkq=Vv[lane*n+q];
                    Vv[lane*n+p]=c*vkp-s*vkq; Vv[lane*n+q]=s*vkp+c*vkq;
                }
                __syncwarp();
                if (lane<n){
                    float apk=A[p*n+lane], aqk=A[q*n+lane];
                    A[p*n+lane]=c*apk-s*aqk; A[q*n+lane]=s*apk+c*aqk;
                }
            }
            __syncwarp();
        }
    }
    __syncwarp();
}

__device__ __forceinline__ void eigh4_log(const float* m, float* out){
    float a[16], v[16];
    #pragma unroll
    for (int i=0;i<16;i++){ a[i]=m[i]; v[i]=((i%5)==0)?1.f:0.f; }
    float nrm=0.f;
    #pragma unroll
    for (int i=0;i<16;i++) nrm+=a[i]*a[i];
    float thr=nrm*1e-15f+1e-38f;
    for (int sw=0;sw<10;sw++){
        bool rot=false;
        #pragma unroll
        for (int p=0;p<3;p++){
            #pragma unroll
            for (int q=p+1;q<4;q++){
                float apq=a[p*4+q];
                if (apq*apq>thr){
                    rot=true;
                    float app=a[p*5], aqq=a[q*5];
                    float tau=(aqq-app)/(2.f*apq);
                    float t=copysignf(1.f,tau)/(fabsf(tau)+sqrtf(1.f+tau*tau));
                    float c=rsqrtf(1.f+t*t), s=t*c;
                    #pragma unroll
                    for (int k2=0;k2<4;k2++){
                        float akp=a[k2*4+p], akq=a[k2*4+q];
                        a[k2*4+p]=c*akp-s*akq; a[k2*4+q]=s*akp+c*akq;
                        float vkp=v[k2*4+p], vkq=v[k2*4+q];
                        v[k2*4+p]=c*vkp-s*vkq; v[k2*4+q]=s*vkp+c*vkq;
                    }
                    #pragma unroll
                    for (int k2=0;k2<4;k2++){
                        float apk=a[p*4+k2], aqk=a[q*4+k2];
                        a[p*4+k2]=c*apk-s*aqk; a[q*4+k2]=s*apk+c*aqk;
                    }
                }
            }
        }
        if (!rot) break;
    }
    float fw[4];
    #pragma unroll
    for (int i=0;i<4;i++) fw[i]=logf(fmaxf(a[i*5],1e-9f));
    #pragma unroll
    for (int i=0;i<16;i++){
        int r2=i/4, c2=i%4;
        float acc=0.f;
        #pragma unroll
        for (int k2=0;k2<4;k2++) acc+=v[r2*4+k2]*fw[k2]*v[c2*4+k2];
        out[i]=acc;
    }
}

__global__ void k_conv1(const float* __restrict__ x, const float* __restrict__ w,
                        const float* __restrict__ cb, const float* __restrict__ bg,
                        const float* __restrict__ bb, const float* __restrict__ bm,
                        const float* __restrict__ bv){
    __shared__ float sw[C1*C1];
    __shared__ float ssc[C1], ssh[C1];
    int tid=threadIdx.x;
    for (int i=tid;i<C1*C1;i+=blockDim.x) sw[i]=w[i];
    if (tid<C1){
        float sc=bg[tid]*rsqrtf(bv[tid]+1e-5f);
        ssc[tid]=sc; ssh[tid]=bb[tid]+(cb[tid]-bm[tid])*sc;
    }
    __syncthreads();
    int b=blockIdx.y; int t=blockIdx.x*blockDim.x+tid;
    if (t>=T0) return;
    float xv[C1];
    #pragma unroll
    for (int h=0;h<C1;h++) xv[h]=x[(b*C1+h)*T0+t];
    #pragma unroll 1
    for (int o=0;o<C1;o++){
        float acc=0.f;
        #pragma unroll
        for (int h=0;h<C1;h++) acc+=xv[h]*sw[o*C1+h];
        g_y1[(b*C1+o)*T0+t]=acc*ssc[o]+ssh[o];
    }
}

__global__ void k_conv2(const float* __restrict__ w2, const float* __restrict__ cb,
                        const float* __restrict__ bg, const float* __restrict__ bb,
                        const float* __restrict__ bm, const float* __restrict__ bv){
    __shared__ float sw[C2*C1*12];
    __shared__ float sy[C1*(TW+12)];
    __shared__ float ssc[C2], ssh[C2];
    int tid=threadIdx.x;
    for (int i=tid;i<C2*C1*12;i+=TW) sw[i]=w2[i];
    if (tid<C2){
        float sc=bg[tid]*rsqrtf(bv[tid]+1e-5f);
        ssc[tid]=sc; ssh[tid]=bb[tid]+(cb[tid]-bm[tid])*sc;
    }
    int b=blockIdx.y; int t0=blockIdx.x*TW;
    for (int i=tid;i<C1*(TW+12);i+=TW){
        int c=i/(TW+12), u=i%(TW+12);
        int tt=t0-6+u;
        sy[i]=(tt>=0 && tt<T0)? g_y1[(b*C1+c)*T0+tt] : 0.f;
    }
    __syncthreads();
    int t=t0+tid;
    if (t>=T1C) return;
    float acc[C2];
    #pragma unroll
    for (int o=0;o<C2;o++) acc[o]=0.f;
    for (int c=0;c<C1;c++){
        float yv[12];
        #pragma unroll
        for (int kk=0;kk<12;kk++) yv[kk]=sy[c*(TW+12)+tid+kk];
        #pragma unroll 1
        for (int o=0;o<C2;o++){
            float a=acc[o];
            #pragma unroll
            for (int kk=0;kk<12;kk++) a+=yv[kk]*sw[(o*C1+c)*12+kk];
            acc[o]=a;
        }
    }
    #pragma unroll 1
    for (int o=0;o<C2;o++) g_sig[(b*C2+o)*T1C+t]=acc[o]*ssc[o]+ssh[o];
}

__global__ void k_cov(){
    __shared__ float s[C2*334];
    __shared__ float cc[325];
    __shared__ float tr_s;
    int u=blockIdx.x, b=u/NEP, e=u%NEP;
    int off=e*334; int L=(e==2)?333:334;
    int tid=threadIdx.x;
    for (int idx=tid; idx<C2*L; idx+=256){
        int c=idx/L, t=idx%L;
        s[c*334+t]=g_sig[(b*C2+c)*T1C+off+t];
    }
    __syncthreads();
    if (tid<C2){
        float acc=0.f;
        for (int t=0;t<L;t++) acc+=s[tid*334+t];
        float mean=acc/(float)L;
        for (int t=0;t<L;t++) s[tid*334+t]-=mean;
    }
    __syncthreads();
    for (int r=tid;r<325;r+=256){
        int i=0, rr=r;
        while (rr>=C2-i){ rr-=C2-i; i++; }
        int j=i+rr;
        float acc=0.f;
        for (int t=0;t<L;t++) acc+=s[i*334+t]*s[j*334+t];
        cc[r]=acc/(float)(L-1);
    }
    __syncthreads();
    if (tid==0){
        float tr=0.f;
        for (int i=0;i<C2;i++) tr+=cc[i*C2 - i*(i-1)/2];
        tr_s=tr;
    }
    __syncthreads();
    float inv=1.f/tr_s;
    float* dst=g_cov+u*625;
    for (int e2=tid;e2<625;e2+=256){
        int i=e2/25, j=e2%25;
        int ii=min(i,j), jj=max(i,j);
        float v=cc[ii*C2 - ii*(ii-1)/2 + (jj-ii)]*inv;
        if (i==j) v+=1e-5f;
        dst[e2]=v;
    }
}

__global__ void k_qk(const float* __restrict__ sk0,const float* __restrict__ sk1,
                     const float* __restrict__ sk2,const float* __restrict__ sk3,
                     const float* __restrict__ sq3){
    __shared__ float scov[4][625];
    __shared__ float sK[4][31*16];
    int warp=threadIdx.x>>5, lane=threadIdx.x&31;
    int u=blockIdx.x*4+warp;
    const float* cov=g_cov+u*625;
    for (int e=lane;e<625;e+=32) scov[warp][e]=cov[e];
    __syncwarp();
    if (lane<31){
        int i=(lane==30)?29:lane;
        int k,pr,pc,gi; patch_info(i,k,pr,pc,gi);
        int kk=k*k;
        const float* W=(lane==30)? sq3 : (gi==0?sk0:gi==1?sk1:gi==2?sk2:sk3);
        float Km[16];
        #pragma unroll
        for (int e=0;e<16;e++) Km[e]=0.f;
        for (int c=0;c<kk;c++){
            int ic=(pr+c/k)*5 + pc + c%k;
            float sa[4]={0.f,0.f,0.f,0.f};
            for (int r=0;r<kk;r++){
                int ir=(pr+r/k)*5 + pc + r%k;
                float xx=scov[warp][ir*25+ic];
                #pragma unroll
                for (int a=0;a<4;a++) sa[a]+=W[r*4+a]*xx;
            }
            #pragma unroll
            for (int a=0;a<4;a++)
                #pragma unroll
                for (int b2=0;b2<4;b2++) Km[a*4+b2]+=sa[a]*W[c*4+b2];
        }
        #pragma unroll
        for (int d=0;d<4;d++) Km[d*5]+=2.5e-5f*(1.f+d);
        float logm[16];
        eigh4_log(Km, logm);
        #pragma unroll
        for (int e=0;e<16;e++) sK[warp][lane*16+e]=logm[e];
    }
    __syncwarp();
    float scval=-1e30f;
    if (lane<30){
        float kn=0.f,cr=0.f,qn=0.f;
        #pragma unroll
        for (int e=0;e<16;e++){
            float a=sK[warp][lane*16+e], q=sK[warp][30*16+e];
            kn+=a*a; cr+=a*q; qn+=q*q;
        }
        float E=fmaxf(kn+qn-2.f*cr,0.f);
        scval=1.f/(1.f+log1pf(E));
    }
    float mx=scval;
    #pragma unroll
    for (int o=16;o;o>>=1) mx=fmaxf(mx,__shfl_xor_sync(0xffffffffu,mx,o));
    float ev=(lane<30)?expf(scval-mx):0.f;
    float sm=warp_sum(ev);
    if (lane<30) g_p[u*30+lane]=ev/sm;
}

__global__ void k_logV(const float* __restrict__ sv0,const float* __restrict__ sv1,
                       const float* __restrict__ sv2,const float* __restrict__ sv3){
    __shared__ float sh[WJ][1250];
    __shared__ int swl[WJ][300];
    __shared__ int sp[300];
    pairs_init(sp,25);
    int warp=threadIdx.x>>5, lane=threadIdx.x&31;
    int gw=blockIdx.x*WJ+warp;
    if (gw>=NU*MM) return;
    int u=gw/MM, i=gw%MM;
    float* A=sh[warp]; float* V=A+625;
    int k,pr,pc,gi; patch_info(i,k,pr,pc,gi);
    int kk=k*k;
    const float* sv=(gi==0?sv0:gi==1?sv1:gi==2?sv2:sv3);
    const float* cov=g_cov+u*625;
    for (int e=lane;e<kk*kk;e+=32){
        int r=e/kk, c=e%kk;
        int ir=(pr+r/k)*5+pc+r%k;
        int ic=(pr+c/k)*5+pc+c%k;
        A[e]=cov[ir*25+ic];
    }
    __syncwarp();
    for (int e=lane;e<kk*25;e+=32){
        int r=e/25, b=e%25;
        float acc=0.f;
        for (int c=0;c<kk;c++) acc+=A[r*kk+c]*sv[c*25+b];
        V[e]=acc;
    }
    __syncwarp();
    for (int e=lane;e<625;e+=32){
        int a=e/25, b=e%25;
        float acc=0.f;
        for (int r=0;r<kk;r++) acc+=sv[r*25+a]*V[r*25+b];
        if (a==b) acc+=4e-6f*(1.f+a);
        A[e]=acc;
    }
    __syncwarp();
    warp_jacobi(A,V,25,sp,300,swl[warp]);
    if (lane<25){ float d=A[lane*26]; A[lane*26]=logf(fmaxf(d,1e-9f)); }
    __syncwarp();
    float* out=g_V+(size_t)gw*625;
    for (int e=lane;e<625;e+=32){
        int a=e/25, b=e%25;
        float acc=0.f;
        for (int kx=0;kx<25;kx++) acc+=V[a*25+kx]*A[kx*26]*V[b*25+kx];
        out[e]=acc;
    }
}

__global__ void k_att1(){
    __shared__ float sh[WJ][1250];
    __shared__ int swl[WJ][300];
    __shared__ int sp[300];
    __shared__ float pp[WJ][30];
    pairs_init(sp,25);
    int warp=threadIdx.x>>5, lane=threadIdx.x&31;
    int u=blockIdx.x*WJ+warp;
    if (u>=NU) return;
    float* A=sh[warp]; float* V=A+625;
    if (lane<30) pp[warp][lane]=g_p[u*30+lane];
    __syncwarp();
    const float* Vb=g_V+(size_t)u*30*625;
    for (int e=lane;e<625;e+=32){
        float acc=0.f;
        #pragma unroll 5
        for (int i=0;i<30;i++) acc+=pp[warp][i]*Vb[(size_t)i*625+e];
        A[e]=acc;
    }
    __syncwarp();
    warp_jacobi(A,V,25,sp,300,swl[warp]);
    if (lane<25) A[lane*26]=fmaxf(expf(A[lane*26]),1e-4f);
    __syncwarp();
    float* dst=g_xm+u*625;
    for (int e=lane;e<625;e+=32){
        int a=e/25, b=e%25;
        float acc=0.f;
        for (int kx=0;kx<25;kx++) acc+=V[a*25+kx]*A[kx*26]*V[b*25+kx];
        dst[e]=acc;
    }
}

__global__ void k_s2log(const float* __restrict__ mq,const float* __restrict__ mk,
                        const float* __restrict__ mv){
    __shared__ float sh[WJ][1250];
    __shared__ int swl[WJ][160];
    __shared__ int sp[153];
    pairs_init(sp,18);
    int warp=threadIdx.x>>5, lane=threadIdx.x&31;
    int id=blockIdx.x*WJ+warp;
    if (id>=BB*9) return;
    int b=id/9, rem=id%9, t=rem/3, c=rem%3;
    float* A=sh[warp]; float* V=A+625;
    const float* W=(c==0?mq:(c==1?mk:mv));
    const float* X=g_xm+(b*3+t)*625;
    for (int e=lane;e<450;e+=32){
        int r=e/18, a=e%18;
        float acc=0.f;
        for (int cc=0;cc<25;cc++) acc+=X[r*25+cc]*W[cc*18+a];
        V[e]=acc;
    }
    __syncwarp();
    for (int e=lane;e<324;e+=32){
        int a=e/18, bb=e%18;
        float acc=0.f;
        for (int r=0;r<25;r++) acc+=W[r*18+a]*V[r*18+bb];
        A[e]=acc;
    }
    __syncwarp();
    warp_jacobi(A,V,18,sp,153,swl[warp]);
    if (lane<18) A[lane*19]=logf(fmaxf(A[lane*19],1e-9f));
    __syncwarp();
    float* dst=(c==0?g_logQ2:(c==1?g_logK2:g_logV2))+(b*3+t)*324;
    for (int e=lane;e<324;e+=32){
        int a=e/18, bb=e%18;
        float acc=0.f;
        for (int kx=0;kx<18;kx++) acc+=V[a*18+kx]*A[kx*19]*V[bb*18+kx];
        dst[e]=acc;
    }
}

__global__ void k_s2att(){
    __shared__ float sh[WJ][1250];
    __shared__ int swl[WJ][160];
    __shared__ int sp[153];
    pairs_init(sp,18);
    int warp=threadIdx.x>>5, lane=threadIdx.x&31;
    int id=blockIdx.x*WJ+warp;
    if (id>=BB*3) return;
    int b=id/3, j=id%3;
    float* A=sh[warp]; float* V=A+625;
    const float* lQ=g_logQ2+(b*3+j)*324;
    float qn=0.f;
    for (int e=lane;e<324;e+=32){ float v=lQ[e]; qn+=v*v; }
    qn=warp_sum(qn);
    float p3[3];
    #pragma unroll
    for (int i=0;i<3;i++){
        const float* lK=g_logK2+(b*3+i)*324;
        float kn=0.f, cr=0.f;
        for (int e=lane;e<324;e+=32){ float a=lK[e], q=lQ[e]; kn+=a*a; cr+=a*q; }
        kn=warp_sum(kn); cr=warp_sum(cr);
        float E=fmaxf(kn+qn-2.f*cr,0.f);
        p3[i]=1.f/(1.f+log1pf(E));
    }
    float mx=fmaxf(p3[0],fmaxf(p3[1],p3[2]));
    float sm=0.f;
    #pragma unroll
    for (int i=0;i<3;i++){ p3[i]=expf(p3[i]-mx); sm+=p3[i]; }
    #pragma unroll
    for (int i=0;i<3;i++) p3[i]/=sm;
    for (int e=lane;e<324;e+=32){
        float acc=0.f;
        #pragma unroll
        for (int i=0;i<3;i++) acc+=p3[i]*g_logV2[(b*3+i)*324+e];
        A[e]=acc;
    }
    __syncwarp();
    warp_jacobi(A,V,18,sp,153,swl[warp]);
    if (lane<18) A[lane*19]=fmaxf(A[lane*19], -9.210340371976184f);
    __syncwarp();
    for (int r=lane;r<171;r+=32){
        int ii=0, rr=r;
        while (rr>=18-ii){ rr-=18-ii; ii++; }
        int jj=ii+rr;
        float acc=0.f;
        for (int kx=0;kx<18;kx++) acc+=V[ii*18+kx]*A[kx*19]*V[jj*18+kx];
        float coef=(ii==jj)?1.f:1.41421356237309515f;
        g_feat[b*513 + j*171 + r]=acc*coef;
    }
}

__global__ void k_head(const float* __restrict__ lw, const float* __restrict__ lb,
                       float* __restrict__ out){
    int b=blockIdx.x; int o=threadIdx.x>>5; int lane=threadIdx.x&31;
    if (o>=4) return;
    float acc=0.f;
    for (int r=lane;r<513;r+=32) acc+=g_feat[b*513+r]*lw[o*513+r];
    acc=warp_sum(acc);
    if (lane==0) out[b*4+o]=acc+lb[o];
}

extern "C" void kernel_launch(void* const* d_in, const int* in_sizes, int n_in,
                              void* d_out, int out_size){
    const float* x   =(const float*)d_in[0];
    const float* c1w =(const float*)d_in[1];
    const float* c1b =(const float*)d_in[2];
    const float* bn1g=(const float*)d_in[3];
    const float* bn1b=(const float*)d_in[4];
    const float* bn1m=(const float*)d_in[5];
    const float* bn1v=(const float*)d_in[6];
    const float* c2w =(const float*)d_in[7];
    const float* c2b =(const float*)d_in[8];
    const float* bn2g=(const float*)d_in[9];
    const float* bn2b=(const float*)d_in[10];
    const float* bn2m=(const float*)d_in[11];
    const float* bn2v=(const float*)d_in[12];
    bool inter = (in_sizes[14]==16);
    const float *sk[4], *sv[4], *sq3p;
    if (inter){
        sq3p=(const float*)d_in[13+3*3];
        for (int g=0; g<4; g++){
            sk[g]=(const float*)d_in[14+3*g];
            sv[g]=(const float*)d_in[15+3*g];
        }
    } else {
        sq3p=(const float*)d_in[16];
        for (int g=0; g<4; g++){
            sk[g]=(const float*)d_in[17+g];
            sv[g]=(const float*)d_in[21+g];
        }
    }
    const float* mq=(const float*)d_in[25];
    const float* mk=(const float*)d_in[26];
    const float* mv=(const float*)d_in[27];
    const float* lw=(const float*)d_in[28];
    const float* lb=(const float*)d_in[29];

    k_conv1<<<dim3(8,BB),128>>>(x,c1w,c1b,bn1g,bn1b,bn1m,bn1v);
    k_conv2<<<dim3(8,BB),128>>>(c2w,c2b,bn2g,bn2b,bn2m,bn2v);
    k_cov  <<<NU,256>>>();
    k_qk   <<<NU/4,128>>>(sk[0],sk[1],sk[2],sk[3],sq3p);
    k_logV <<<(NU*MM+WJ-1)/WJ,WJ*32>>>(sv[0],sv[1],sv[2],sv[3]);
    k_att1 <<<(NU+WJ-1)/WJ,WJ*32>>>();
    k_s2log<<<(BB*9+WJ-1)/WJ,WJ*32>>>(mq,mk,mv);
    k_s2att<<<(BB*3+WJ-1)/WJ,WJ*32>>>();
    k_head <<<BB,128>>>(lw,lb,(float*)d_out);
}

// round 6
// speedup vs baseline: 2.8992x; 1.5064x over previous
#include <cuda_runtime.h>
#include <cuda_bf16.h>

#define BB   256
#define T0   1000
#define T1C  1001
#define C1   22
#define C2   25
#define NEP  3
#define NU   (BB*NEP)
#define MM   30
#define TW   128
#define WJ   8

__device__ float g_y1  [BB*C1*T0];
__device__ float g_sig [BB*C2*T1C];
__device__ float g_cov [NU*625];
__device__ float g_V   [NU*MM*625];
__device__ float g_p   [NU*MM];
__device__ float g_xm  [NU*625];
__device__ float g_logQ2[BB*3*324];
__device__ float g_logK2[BB*3*324];
__device__ float g_logV2[BB*3*324];
__device__ float g_feat [BB*513];

__device__ __forceinline__ float warp_sum(float v){
    #pragma unroll
    for (int o=16;o;o>>=1) v += __shfl_xor_sync(0xffffffffu, v, o);
    return v;
}

__device__ __forceinline__ void patch_info(int i, int&k, int&pr, int&pc, int&gi){
    if (i<16){ gi=0;k=2;pr=i/4;pc=i%4; }
    else if (i<25){ gi=1;k=3;int p=i-16;pr=p/3;pc=p%3; }
    else if (i<29){ gi=2;k=4;int p=i-25;pr=p/2;pc=p%2; }
    else { gi=3;k=5;pr=0;pc=0; }
}

// round-robin tournament schedule: R rounds x P pairs, disjoint within a round
__device__ void sched_init(unsigned short* sched, int n){
    int m=(n+1)&~1, P=m>>1, R=m-1;
    for (int idx=threadIdx.x; idx<R*P; idx+=blockDim.x){
        int r=idx/P, i=idx%P;
        int j=m-1-i;
        int a=(i==0)?0:(1+(r+i-1)%(m-1));
        int b=1+(r+j-1)%(m-1);
        int p=min(a,b), q=max(a,b);
        sched[idx]=(q<n)? (unsigned short)((p<<8)|q) : (unsigned short)0xFFFF;
    }
    __syncthreads();
}

// Tournament-batched Jacobi: disjoint active rotations applied in parallel.
__device__ void warp_jacobi(float* A, float* Vv, int n, const unsigned short* sched,
                            int R, int P, float* cb, float* sb, int* pqb){
    int lane=threadIdx.x&31;
    for (int e=lane;e<n*n;e+=32) Vv[e]=((e%(n+1))==0)?1.f:0.f;
    float nrm=0.f;
    for (int e=lane;e<n*n;e+=32) nrm+=A[e]*A[e];
    nrm=warp_sum(nrm);
    float thr=nrm*1e-15f+1e-38f;
    __syncwarp();
    for (int sweep=0;sweep<24;sweep++){
        int any=0;
        for (int r=0;r<R;r++){
            bool act=false; int pq=0; float c0=1.f,s0=0.f;
            if (lane<P){
                pq=sched[r*P+lane];
                if (pq!=0xFFFF){
                    int p=pq>>8, q=pq&255;
                    float apq=A[p*n+q];
                    if (apq*apq>thr){
                        act=true;
                        float app=A[p*n+p], aqq=A[q*n+q];
                        float tau=(aqq-app)/(2.f*apq);
                        float t=copysignf(1.f,tau)/(fabsf(tau)+sqrtf(1.f+tau*tau));
                        c0=rsqrtf(1.f+t*t); s0=t*c0;
                    }
                }
            }
            unsigned msk=__ballot_sync(0xffffffffu,act);
            int cnt=__popc(msk);
            if (!cnt) continue;
            any=1;
            if (act){
                int pos=__popc(msk&((1u<<lane)-1u));
                pqb[pos]=pq; cb[pos]=c0; sb[pos]=s0;
            }
            __syncwarp();
            if (lane<n){
                for (int i=0;i<cnt;i++){
                    int pq2=pqb[i]; int p=pq2>>8, q=pq2&255;
                    float cc=cb[i], ss=sb[i];
                    float akp=A[lane*n+p], akq=A[lane*n+q];
                    A[lane*n+p]=cc*akp-ss*akq; A[lane*n+q]=ss*akp+cc*akq;
                    float vkp=Vv[lane*n+p], vkq=Vv[lane*n+q];
                    Vv[lane*n+p]=cc*vkp-ss*vkq; Vv[lane*n+q]=ss*vkp+cc*vkq;
                }
            }
            __syncwarp();
            if (lane<n){
                for (int i=0;i<cnt;i++){
                    int pq2=pqb[i]; int p=pq2>>8, q=pq2&255;
                    float cc=cb[i], ss=sb[i];
                    float apk=A[p*n+lane], aqk=A[q*n+lane];
                    A[p*n+lane]=cc*apk-ss*aqk; A[q*n+lane]=ss*apk+cc*aqk;
                }
            }
            __syncwarp();
        }
        if (!any) break;
    }
    __syncwarp();
}

__device__ __forceinline__ void eigh4_log(const float* m, float* out){
    float a[16], v[16];
    #pragma unroll
    for (int i=0;i<16;i++){ a[i]=m[i]; v[i]=((i%5)==0)?1.f:0.f; }
    float nrm=0.f;
    #pragma unroll
    for (int i=0;i<16;i++) nrm+=a[i]*a[i];
    float thr=nrm*1e-15f+1e-38f;
    for (int sw=0;sw<10;sw++){
        bool rot=false;
        #pragma unroll
        for (int p=0;p<3;p++){
            #pragma unroll
            for (int q=p+1;q<4;q++){
                float apq=a[p*4+q];
                if (apq*apq>thr){
                    rot=true;
                    float app=a[p*5], aqq=a[q*5];
                    float tau=(aqq-app)/(2.f*apq);
                    float t=copysignf(1.f,tau)/(fabsf(tau)+sqrtf(1.f+tau*tau));
                    float c=rsqrtf(1.f+t*t), s=t*c;
                    #pragma unroll
                    for (int k2=0;k2<4;k2++){
                        float akp=a[k2*4+p], akq=a[k2*4+q];
                        a[k2*4+p]=c*akp-s*akq; a[k2*4+q]=s*akp+c*akq;
                        float vkp=v[k2*4+p], vkq=v[k2*4+q];
                        v[k2*4+p]=c*vkp-s*vkq; v[k2*4+q]=s*vkp+c*vkq;
                    }
                    #pragma unroll
                    for (int k2=0;k2<4;k2++){
                        float apk=a[p*4+k2], aqk=a[q*4+k2];
                        a[p*4+k2]=c*apk-s*aqk; a[q*4+k2]=s*apk+c*aqk;
                    }
                }
            }
        }
        if (!rot) break;
    }
    float fw[4];
    #pragma unroll
    for (int i=0;i<4;i++) fw[i]=logf(fmaxf(a[i*5],1e-9f));
    #pragma unroll
    for (int i=0;i<16;i++){
        int r2=i/4, c2=i%4;
        float acc=0.f;
        #pragma unroll
        for (int k2=0;k2<4;k2++) acc+=v[r2*4+k2]*fw[k2]*v[c2*4+k2];
        out[i]=acc;
    }
}

__global__ void k_conv1(const float* __restrict__ x, const float* __restrict__ w,
                        const float* __restrict__ cb, const float* __restrict__ bg,
                        const float* __restrict__ bb, const float* __restrict__ bm,
                        const float* __restrict__ bv){
    __shared__ float sw[C1*C1];
    __shared__ float ssc[C1], ssh[C1];
    int tid=threadIdx.x;
    for (int i=tid;i<C1*C1;i+=blockDim.x) sw[i]=w[i];
    if (tid<C1){
        float sc=bg[tid]*rsqrtf(bv[tid]+1e-5f);
        ssc[tid]=sc; ssh[tid]=bb[tid]+(cb[tid]-bm[tid])*sc;
    }
    __syncthreads();
    int b=blockIdx.y; int t=blockIdx.x*blockDim.x+tid;
    if (t>=T0) return;
    float xv[C1];
    #pragma unroll
    for (int h=0;h<C1;h++) xv[h]=x[(b*C1+h)*T0+t];
    #pragma unroll 1
    for (int o=0;o<C1;o++){
        float acc=0.f;
        #pragma unroll
        for (int h=0;h<C1;h++) acc+=xv[h]*sw[o*C1+h];
        g_y1[(b*C1+o)*T0+t]=acc*ssc[o]+ssh[o];
    }
}

__global__ void k_conv2(const float* __restrict__ w2, const float* __restrict__ cb,
                        const float* __restrict__ bg, const float* __restrict__ bb,
                        const float* __restrict__ bm, const float* __restrict__ bv){
    __shared__ float sw[C2*C1*12];
    __shared__ float sy[C1*(TW+12)];
    __shared__ float ssc[C2], ssh[C2];
    int tid=threadIdx.x;
    for (int i=tid;i<C2*C1*12;i+=TW) sw[i]=w2[i];
    if (tid<C2){
        float sc=bg[tid]*rsqrtf(bv[tid]+1e-5f);
        ssc[tid]=sc; ssh[tid]=bb[tid]+(cb[tid]-bm[tid])*sc;
    }
    int b=blockIdx.y; int t0=blockIdx.x*TW;
    for (int i=tid;i<C1*(TW+12);i+=TW){
        int c=i/(TW+12), u=i%(TW+12);
        int tt=t0-6+u;
        sy[i]=(tt>=0 && tt<T0)? g_y1[(b*C1+c)*T0+tt] : 0.f;
    }
    __syncthreads();
    int t=t0+tid;
    if (t>=T1C) return;
    float acc[C2];
    #pragma unroll
    for (int o=0;o<C2;o++) acc[o]=0.f;
    for (int c=0;c<C1;c++){
        float yv[12];
        #pragma unroll
        for (int kk=0;kk<12;kk++) yv[kk]=sy[c*(TW+12)+tid+kk];
        #pragma unroll 1
        for (int o=0;o<C2;o++){
            float a=acc[o];
            #pragma unroll
            for (int kk=0;kk<12;kk++) a+=yv[kk]*sw[(o*C1+c)*12+kk];
            acc[o]=a;
        }
    }
    #pragma unroll 1
    for (int o=0;o<C2;o++) g_sig[(b*C2+o)*T1C+t]=acc[o]*ssc[o]+ssh[o];
}

__global__ void k_cov(){
    __shared__ float s[C2*334];
    __shared__ float cc[325];
    __shared__ float tr_s;
    int u=blockIdx.x, b=u/NEP, e=u%NEP;
    int off=e*334; int L=(e==2)?333:334;
    int tid=threadIdx.x;
    for (int idx=tid; idx<C2*L; idx+=256){
        int c=idx/L, t=idx%L;
        s[c*334+t]=g_sig[(b*C2+c)*T1C+off+t];
    }
    __syncthreads();
    if (tid<C2){
        float acc=0.f;
        for (int t=0;t<L;t++) acc+=s[tid*334+t];
        float mean=acc/(float)L;
        for (int t=0;t<L;t++) s[tid*334+t]-=mean;
    }
    __syncthreads();
    for (int r=tid;r<325;r+=256){
        int i=0, rr=r;
        while (rr>=C2-i){ rr-=C2-i; i++; }
        int j=i+rr;
        float acc=0.f;
        for (int t=0;t<L;t++) acc+=s[i*334+t]*s[j*334+t];
        cc[r]=acc/(float)(L-1);
    }
    __syncthreads();
    if (tid==0){
        float tr=0.f;
        for (int i=0;i<C2;i++) tr+=cc[i*C2 - i*(i-1)/2];
        tr_s=tr;
    }
    __syncthreads();
    float inv=1.f/tr_s;
    float* dst=g_cov+u*625;
    for (int e2=tid;e2<625;e2+=256){
        int i=e2/25, j=e2%25;
        int ii=min(i,j), jj=max(i,j);
        float v=cc[ii*C2 - ii*(ii-1)/2 + (jj-ii)]*inv;
        if (i==j) v+=1e-5f;
        dst[e2]=v;
    }
}

__global__ void k_qk(const float* __restrict__ sk0,const float* __restrict__ sk1,
                     const float* __restrict__ sk2,const float* __restrict__ sk3,
                     const float* __restrict__ sq3){
    __shared__ float scov[4][625];
    __shared__ float sK[4][31*16];
    int warp=threadIdx.x>>5, lane=threadIdx.x&31;
    int u=blockIdx.x*4+warp;
    const float* cov=g_cov+u*625;
    for (int e=lane;e<625;e+=32) scov[warp][e]=cov[e];
    __syncwarp();
    if (lane<31){
        int i=(lane==30)?29:lane;
        int k,pr,pc,gi; patch_info(i,k,pr,pc,gi);
        int kk=k*k;
        const float* W=(lane==30)? sq3 : (gi==0?sk0:gi==1?sk1:gi==2?sk2:sk3);
        float Km[16];
        #pragma unroll
        for (int e=0;e<16;e++) Km[e]=0.f;
        for (int c=0;c<kk;c++){
            int ic=(pr+c/k)*5 + pc + c%k;
            float sa[4]={0.f,0.f,0.f,0.f};
            for (int r=0;r<kk;r++){
                int ir=(pr+r/k)*5 + pc + r%k;
                float xx=scov[warp][ir*25+ic];
                #pragma unroll
                for (int a=0;a<4;a++) sa[a]+=W[r*4+a]*xx;
            }
            #pragma unroll
            for (int a=0;a<4;a++)
                #pragma unroll
                for (int b2=0;b2<4;b2++) Km[a*4+b2]+=sa[a]*W[c*4+b2];
        }
        #pragma unroll
        for (int d=0;d<4;d++) Km[d*5]+=2.5e-5f*(1.f+d);
        float logm[16];
        eigh4_log(Km, logm);
        #pragma unroll
        for (int e=0;e<16;e++) sK[warp][lane*16+e]=logm[e];
    }
    __syncwarp();
    float scval=-1e30f;
    if (lane<30){
        float kn=0.f,cr=0.f,qn=0.f;
        #pragma unroll
        for (int e=0;e<16;e++){
            float a=sK[warp][lane*16+e], q=sK[warp][30*16+e];
            kn+=a*a; cr+=a*q; qn+=q*q;
        }
        float E=fmaxf(kn+qn-2.f*cr,0.f);
        scval=1.f/(1.f+log1pf(E));
    }
    float mx=scval;
    #pragma unroll
    for (int o=16;o;o>>=1) mx=fmaxf(mx,__shfl_xor_sync(0xffffffffu,mx,o));
    float ev=(lane<30)?expf(scval-mx):0.f;
    float sm=warp_sum(ev);
    if (lane<30) g_p[u*30+lane]=ev/sm;
}

__global__ void k_logV(const float* __restrict__ sv0,const float* __restrict__ sv1,
                       const float* __restrict__ sv2,const float* __restrict__ sv3){
    __shared__ float sh[WJ][1250];
    __shared__ float scb[WJ][16], ssb[WJ][16];
    __shared__ int spq[WJ][16];
    __shared__ unsigned short sched[325];
    sched_init(sched,25);
    int warp=threadIdx.x>>5, lane=threadIdx.x&31;
    int gw=blockIdx.x*WJ+warp;
    if (gw>=NU*MM) return;
    int u=gw/MM, i=gw%MM;
    float* A=sh[warp]; float* V=A+625;
    int k,pr,pc,gi; patch_info(i,k,pr,pc,gi);
    int kk=k*k;
    const float* sv=(gi==0?sv0:gi==1?sv1:gi==2?sv2:sv3);
    const float* cov=g_cov+u*625;
    for (int e=lane;e<kk*kk;e+=32){
        int r=e/kk, c=e%kk;
        int ir=(pr+r/k)*5+pc+r%k;
        int ic=(pr+c/k)*5+pc+c%k;
        A[e]=cov[ir*25+ic];
    }
    __syncwarp();
    for (int e=lane;e<kk*25;e+=32){
        int r=e/25, b=e%25;
        float acc=0.f;
        for (int c=0;c<kk;c++) acc+=A[r*kk+c]*sv[c*25+b];
        V[e]=acc;
    }
    __syncwarp();
    for (int e=lane;e<625;e+=32){
        int a=e/25, b=e%25;
        float acc=0.f;
        for (int r=0;r<kk;r++) acc+=sv[r*25+a]*V[r*25+b];
        if (a==b) acc+=4e-6f*(1.f+a);
        A[e]=acc;
    }
    __syncwarp();
    warp_jacobi(A,V,25,sched,25,13,scb[warp],ssb[warp],spq[warp]);
    if (lane<25){ float d=A[lane*26]; A[lane*26]=logf(fmaxf(d,1e-9f)); }
    __syncwarp();
    float* out=g_V+(size_t)gw*625;
    for (int e=lane;e<625;e+=32){
        int a=e/25, b=e%25;
        float acc=0.f;
        for (int kx=0;kx<25;kx++) acc+=V[a*25+kx]*A[kx*26]*V[b*25+kx];
        out[e]=acc;
    }
}

__global__ void k_att1(){
    __shared__ float sh[WJ][1250];
    __shared__ float scb[WJ][16], ssb[WJ][16];
    __shared__ int spq[WJ][16];
    __shared__ unsigned short sched[325];
    __shared__ float pp[WJ][30];
    sched_init(sched,25);
    int warp=threadIdx.x>>5, lane=threadIdx.x&31;
    int u=blockIdx.x*WJ+warp;
    if (u>=NU) return;
    float* A=sh[warp]; float* V=A+625;
    if (lane<30) pp[warp][lane]=g_p[u*30+lane];
    __syncwarp();
    const float* Vb=g_V+(size_t)u*30*625;
    for (int e=lane;e<625;e+=32){
        float acc=0.f;
        #pragma unroll 5
        for (int i=0;i<30;i++) acc+=pp[warp][i]*Vb[(size_t)i*625+e];
        A[e]=acc;
    }
    __syncwarp();
    warp_jacobi(A,V,25,sched,25,13,scb[warp],ssb[warp],spq[warp]);
    if (lane<25) A[lane*26]=fmaxf(expf(A[lane*26]),1e-4f);
    __syncwarp();
    float* dst=g_xm+u*625;
    for (int e=lane;e<625;e+=32){
        int a=e/25, b=e%25;
        float acc=0.f;
        for (int kx=0;kx<25;kx++) acc+=V[a*25+kx]*A[kx*26]*V[b*25+kx];
        dst[e]=acc;
    }
}

__global__ void k_s2log(const float* __restrict__ mq,const float* __restrict__ mk,
                        const float* __restrict__ mv){
    __shared__ float sh[WJ][1250];
    __shared__ float scb[WJ][16], ssb[WJ][16];
    __shared__ int spq[WJ][16];
    __shared__ unsigned short sched[153];
    sched_init(sched,18);
    int warp=threadIdx.x>>5, lane=threadIdx.x&31;
    int id=blockIdx.x*WJ+warp;
    if (id>=BB*9) return;
    int b=id/9, rem=id%9, t=rem/3, c=rem%3;
    float* A=sh[warp]; float* V=A+625;
    const float* W=(c==0?mq:(c==1?mk:mv));
    const float* X=g_xm+(b*3+t)*625;
    for (int e=lane;e<450;e+=32){
        int r=e/18, a=e%18;
        float acc=0.f;
        for (int cc=0;cc<25;cc++) acc+=X[r*25+cc]*W[cc*18+a];
        V[e]=acc;
    }
    __syncwarp();
    for (int e=lane;e<324;e+=32){
        int a=e/18, bb=e%18;
        float acc=0.f;
        for (int r=0;r<25;r++) acc+=W[r*18+a]*V[r*18+bb];
        A[e]=acc;
    }
    __syncwarp();
    warp_jacobi(A,V,18,sched,17,9,scb[warp],ssb[warp],spq[warp]);
    if (lane<18) A[lane*19]=logf(fmaxf(A[lane*19],1e-9f));
    __syncwarp();
    float* dst=(c==0?g_logQ2:(c==1?g_logK2:g_logV2))+(b*3+t)*324;
    for (int e=lane;e<324;e+=32){
        int a=e/18, bb=e%18;
        float acc=0.f;
        for (int kx=0;kx<18;kx++) acc+=V[a*18+kx]*A[kx*19]*V[bb*18+kx];
        dst[e]=acc;
    }
}

__global__ void k_s2att(){
    __shared__ float sh[WJ][1250];
    __shared__ float scb[WJ][16], ssb[WJ][16];
    __shared__ int spq[WJ][16];
    __shared__ unsigned short sched[153];
    sched_init(sched,18);
    int warp=threadIdx.x>>5, lane=threadIdx.x&31;
    int id=blockIdx.x*WJ+warp;
    if (id>=BB*3) return;
    int b=id/3, j=id%3;
    float* A=sh[warp]; float* V=A+625;
    const float* lQ=g_logQ2+(b*3+j)*324;
    float qn=0.f;
    for (int e=lane;e<324;e+=32){ float v=lQ[e]; qn+=v*v; }
    qn=warp_sum(qn);
    float p3[3];
    #pragma unroll
    for (int i=0;i<3;i++){
        const float* lK=g_logK2+(b*3+i)*324;
        float kn=0.f, cr=0.f;
        for (int e=lane;e<324;e+=32){ float a=lK[e], q=lQ[e]; kn+=a*a; cr+=a*q; }
        kn=warp_sum(kn); cr=warp_sum(cr);
        float E=fmaxf(kn+qn-2.f*cr,0.f);
        p3[i]=1.f/(1.f+log1pf(E));
    }
    float mx=fmaxf(p3[0],fmaxf(p3[1],p3[2]));
    float sm=0.f;
    #pragma unroll
    for (int i=0;i<3;i++){ p3[i]=expf(p3[i]-mx); sm+=p3[i]; }
    #pragma unroll
    for (int i=0;i<3;i++) p3[i]/=sm;
    for (int e=lane;e<324;e+=32){
        float acc=0.f;
        #pragma unroll
        for (int i=0;i<3;i++) acc+=p3[i]*g_logV2[(b*3+i)*324+e];
        A[e]=acc;
    }
    __syncwarp();
    warp_jacobi(A,V,18,sched,17,9,scb[warp],ssb[warp],spq[warp]);
    if (lane<18) A[lane*19]=fmaxf(A[lane*19], -9.210340371976184f);
    __syncwarp();
    for (int r=lane;r<171;r+=32){
        int ii=0, rr=r;
        while (rr>=18-ii){ rr-=18-ii; ii++; }
        int jj=ii+rr;
        float acc=0.f;
        for (int kx=0;kx<18;kx++) acc+=V[ii*18+kx]*A[kx*19]*V[jj*18+kx];
        float coef=(ii==jj)?1.f:1.41421356237309515f;
        g_feat[b*513 + j*171 + r]=acc*coef;
    }
}

__global__ void k_head(const float* __restrict__ lw, const float* __restrict__ lb,
                       float* __restrict__ out){
    int b=blockIdx.x; int o=threadIdx.x>>5; int lane=threadIdx.x&31;
    if (o>=4) return;
    float acc=0.f;
    for (int r=lane;r<513;r+=32) acc+=g_feat[b*513+r]*lw[o*513+r];
    acc=warp_sum(acc);
    if (lane==0) out[b*4+o]=acc+lb[o];
}

extern "C" void kernel_launch(void* const* d_in, const int* in_sizes, int n_in,
                              void* d_out, int out_size){
    const float* x   =(const float*)d_in[0];
    const float* c1w =(const float*)d_in[1];
    const float* c1b =(const float*)d_in[2];
    const float* bn1g=(const float*)d_in[3];
    const float* bn1b=(const float*)d_in[4];
    const float* bn1m=(const float*)d_in[5];
    const float* bn1v=(const float*)d_in[6];
    const float* c2w =(const float*)d_in[7];
    const float* c2b =(const float*)d_in[8];
    const float* bn2g=(const float*)d_in[9];
    const float* bn2b=(const float*)d_in[10];
    const float* bn2m=(const float*)d_in[11];
    const float* bn2v=(const float*)d_in[12];
    bool inter = (in_sizes[14]==16);
    const float *sk[4], *sv[4], *sq3p;
    if (inter){
        sq3p=(const float*)d_in[13+3*3];
        for (int g=0; g<4; g++){
            sk[g]=(const float*)d_in[14+3*g];
            sv[g]=(const float*)d_in[15+3*g];
        }
    } else {
        sq3p=(const float*)d_in[16];
        for (int g=0; g<4; g++){
            sk[g]=(const float*)d_in[17+g];
            sv[g]=(const float*)d_in[21+g];
        }
    }
    const float* mq=(const float*)d_in[25];
    const float* mk=(const float*)d_in[26];
    const float* mv=(const float*)d_in[27];
    const float* lw=(const float*)d_in[28];
    const float* lb=(const float*)d_in[29];

    k_conv1<<<dim3(8,BB),128>>>(x,c1w,c1b,bn1g,bn1b,bn1m,bn1v);
    k_conv2<<<dim3(8,BB),128>>>(c2w,c2b,bn2g,bn2b,bn2m,bn2v);
    k_cov  <<<NU,256>>>();
    k_qk   <<<NU/4,128>>>(sk[0],sk[1],sk[2],sk[3],sq3p);
    k_logV <<<(NU*MM+WJ-1)/WJ,WJ*32>>>(sv[0],sv[1],sv[2],sv[3]);
    k_att1 <<<(NU+WJ-1)/WJ,WJ*32>>>();
    k_s2log<<<(BB*9+WJ-1)/WJ,WJ*32>>>(mq,mk,mv);
    k_s2att<<<(BB*3+WJ-1)/WJ,WJ*32>>>();
    k_head <<<BB,128>>>(lw,lb,(float*)d_out);
}

// round 7
// speedup vs baseline: 3.4495x; 1.1898x over previous
#include <cuda_runtime.h>
#include <cuda_bf16.h>

#define BB   256
#define T0   1000
#define T1C  1001
#define C1   22
#define C2   25
#define NEP  3
#define NU   (BB*NEP)
#define MM   30
#define TW   128
#define WJ   8

__device__ float g_y1  [BB*C1*T0];
__device__ float g_sig [BB*C2*T1C];
__device__ float g_cov [NU*625];
__device__ float g_V   [NU*MM*625];
__device__ float g_p   [NU*MM];
__device__ float g_xm  [NU*625];
__device__ float g_logQ2[BB*3*324];
__device__ float g_logK2[BB*3*324];
__device__ float g_logV2[BB*3*324];
__device__ float g_feat [BB*513];
// group-0 prep outputs
__device__ float g_P2[25*21];
__device__ float g_CZ[4*21];
__device__ float g_E11[16];
__device__ float g_mu[21];

__device__ __forceinline__ float warp_sum(float v){
    #pragma unroll
    for (int o=16;o;o>>=1) v += __shfl_xor_sync(0xffffffffu, v, o);
    return v;
}

__device__ __forceinline__ void patch_info(int i, int&k, int&pr, int&pc, int&gi){
    if (i<16){ gi=0;k=2;pr=i/4;pc=i%4; }
    else if (i<25){ gi=1;k=3;int p=i-16;pr=p/3;pc=p%3; }
    else if (i<29){ gi=2;k=4;int p=i-25;pr=p/2;pc=p%2; }
    else { gi=3;k=5;pr=0;pc=0; }
}

__device__ void sched_init(unsigned short* sched, int n){
    int m=(n+1)&~1, P=m>>1, R=m-1;
    for (int idx=threadIdx.x; idx<R*P; idx+=blockDim.x){
        int r=idx/P, i=idx%P;
        int j=m-1-i;
        int a=(i==0)?0:(1+(r+i-1)%(m-1));
        int b=1+(r+j-1)%(m-1);
        int p=min(a,b), q=max(a,b);
        sched[idx]=(q<n)? (unsigned short)((p<<8)|q) : (unsigned short)0xFFFF;
    }
    __syncthreads();
}

// Tournament-batched Jacobi; preV: eigenvector accumulator preloaded.
__device__ void warp_jacobi(float* A, float* Vv, int n, const unsigned short* sched,
                            int R, int P, float* cb, float* sb, int* pqb, bool preV){
    int lane=threadIdx.x&31;
    if (!preV) for (int e=lane;e<n*n;e+=32) Vv[e]=((e%(n+1))==0)?1.f:0.f;
    float nrm=0.f;
    for (int e=lane;e<n*n;e+=32) nrm+=A[e]*A[e];
    nrm=warp_sum(nrm);
    float thr=nrm*1e-15f+1e-38f;
    __syncwarp();
    for (int sweep=0;sweep<24;sweep++){
        int any=0;
        for (int r=0;r<R;r++){
            bool act=false; int pq=0; float c0=1.f,s0=0.f;
            if (lane<P){
                pq=sched[r*P+lane];
                if (pq!=0xFFFF){
                    int p=pq>>8, q=pq&255;
                    float apq=A[p*n+q];
                    if (apq*apq>thr){
                        act=true;
                        float app=A[p*n+p], aqq=A[q*n+q];
                        float tau=(aqq-app)/(2.f*apq);
                        float t=copysignf(1.f,tau)/(fabsf(tau)+sqrtf(1.f+tau*tau));
                        c0=rsqrtf(1.f+t*t); s0=t*c0;
                    }
                }
            }
            unsigned msk=__ballot_sync(0xffffffffu,act);
            int cnt=__popc(msk);
            if (!cnt) continue;
            any=1;
            if (act){
                int pos=__popc(msk&((1u<<lane)-1u));
                pqb[pos]=pq; cb[pos]=c0; sb[pos]=s0;
            }
            __syncwarp();
            if (lane<n){
                for (int i=0;i<cnt;i++){
                    int pq2=pqb[i]; int p=pq2>>8, q=pq2&255;
                    float cc=cb[i], ss=sb[i];
                    float akp=A[lane*n+p], akq=A[lane*n+q];
                    A[lane*n+p]=cc*akp-ss*akq; A[lane*n+q]=ss*akp+cc*akq;
                    float vkp=Vv[lane*n+p], vkq=Vv[lane*n+q];
                    Vv[lane*n+p]=cc*vkp-ss*vkq; Vv[lane*n+q]=ss*vkp+cc*vkq;
                }
            }
            __syncwarp();
            if (lane<n){
                for (int i=0;i<cnt;i++){
                    int pq2=pqb[i]; int p=pq2>>8, q=pq2&255;
                    float cc=cb[i], ss=sb[i];
                    float apk=A[p*n+lane], aqk=A[q*n+lane];
                    A[p*n+lane]=cc*apk-ss*aqk; A[q*n+lane]=ss*apk+cc*aqk;
                }
            }
            __syncwarp();
        }
        if (!any) break;
    }
    __syncwarp();
}

__device__ __forceinline__ void eigh4_plain(const float* m, float* a, float* v){
    #pragma unroll
    for (int i=0;i<16;i++){ a[i]=m[i]; v[i]=((i%5)==0)?1.f:0.f; }
    float nrm=0.f;
    #pragma unroll
    for (int i=0;i<16;i++) nrm+=a[i]*a[i];
    float thr=nrm*1e-15f+1e-38f;
    for (int sw=0;sw<10;sw++){
        bool rot=false;
        #pragma unroll
        for (int p=0;p<3;p++){
            #pragma unroll
            for (int q=p+1;q<4;q++){
                float apq=a[p*4+q];
                if (apq*apq>thr){
                    rot=true;
                    float app=a[p*5], aqq=a[q*5];
                    float tau=(aqq-app)/(2.f*apq);
                    float t=copysignf(1.f,tau)/(fabsf(tau)+sqrtf(1.f+tau*tau));
                    float c=rsqrtf(1.f+t*t), s=t*c;
                    #pragma unroll
                    for (int k2=0;k2<4;k2++){
                        float akp=a[k2*4+p], akq=a[k2*4+q];
                        a[k2*4+p]=c*akp-s*akq; a[k2*4+q]=s*akp+c*akq;
                        float vkp=v[k2*4+p], vkq=v[k2*4+q];
                        v[k2*4+p]=c*vkp-s*vkq; v[k2*4+q]=s*vkp+c*vkq;
                    }
                    #pragma unroll
                    for (int k2=0;k2<4;k2++){
                        float apk=a[p*4+k2], aqk=a[q*4+k2];
                        a[p*4+k2]=c*apk-s*aqk; a[q*4+k2]=s*apk+c*aqk;
                    }
                }
            }
        }
        if (!rot) break;
    }
}

__device__ __forceinline__ void eigh4_log(const float* m, float* out){
    float a[16], v[16];
    eigh4_plain(m,a,v);
    float fw[4];
    #pragma unroll
    for (int i=0;i<4;i++) fw[i]=logf(fmaxf(a[i*5],1e-9f));
    #pragma unroll
    for (int i=0;i<16;i++){
        int r2=i/4, c2=i%4;
        float acc=0.f;
        #pragma unroll
        for (int k2=0;k2<4;k2++) acc+=v[r2*4+k2]*fw[k2]*v[c2*4+k2];
        out[i]=acc;
    }
}

// one-time prep for group 0: complement basis + fixed transforms
__global__ void k_prep(const float* __restrict__ sv0){
    __shared__ float Wp[21*25];
    __shared__ float F[441];
    __shared__ float Z[441];
    __shared__ float Bm[84];
    __shared__ float cb[16], sb[16];
    __shared__ int pqb[16];
    __shared__ unsigned short sched[231];
    sched_init(sched,21);
    int lane=threadIdx.x;
    if (lane<16){
        int i=lane>>2, j=lane&3;
        float acc=0.f;
        for (int a=0;a<25;a++) acc+=sv0[i*25+a]*(4e-6f*(1.f+a))*sv0[j*25+a];
        g_E11[lane]=acc;
    }
    __syncwarp();
    int rc=0;
    for (int cand=0; cand<25 && rc<21; cand++){
        float v=(lane==cand)?1.f:0.f;
        for (int pass=0;pass<2;pass++){
            for (int i=0;i<4;i++){
                float w=(lane<25)?sv0[i*25+lane]:0.f;
                float d=warp_sum(v*w); v-=d*w;
            }
            for (int i=0;i<rc;i++){
                float w=(lane<25)?Wp[i*25+lane]:0.f;
                float d=warp_sum(v*w); v-=d*w;
            }
        }
        float nn=warp_sum(v*v);
        if (nn>1e-4f){
            float inv=rsqrtf(nn);
            if (lane<25) Wp[rc*25+lane]=v*inv;
            rc++;
        }
        __syncwarp();
    }
    for (int e=lane;e<441;e+=32){
        int m=e/21, n2=e%21;
        float acc=0.f;
        for (int a=0;a<25;a++) acc+=Wp[m*25+a]*(4e-6f*(1.f+a))*Wp[n2*25+a];
        F[e]=acc;
    }
    __syncwarp();
    warp_jacobi(F,Z,21,sched,21,11,cb,sb,pqb,false);
    if (lane<21) g_mu[lane]=F[lane*22];
    for (int e=lane;e<525;e+=32){
        int a=e/21, m=e%21;
        float acc=0.f;
        for (int t=0;t<21;t++) acc+=Wp[t*25+a]*Z[t*21+m];
        g_P2[e]=acc;
    }
    for (int e=lane;e<84;e+=32){
        int i=e/21, t=e%21;
        float acc=0.f;
        for (int a=0;a<25;a++) acc+=sv0[i*25+a]*(4e-6f*(1.f+a))*Wp[t*25+a];
        Bm[e]=acc;
    }
    __syncwarp();
    for (int e=lane;e<84;e+=32){
        int i=e/21, m=e%21;
        float acc=0.f;
        for (int t=0;t<21;t++) acc+=Bm[i*21+t]*Z[t*21+m];
        g_CZ[e]=acc;
    }
}

__global__ void k_conv1(const float* __restrict__ x, const float* __restrict__ w,
                        const float* __restrict__ cb, const float* __restrict__ bg,
                        const float* __restrict__ bb, const float* __restrict__ bm,
                        const float* __restrict__ bv){
    __shared__ float sw[C1*C1];
    __shared__ float ssc[C1], ssh[C1];
    int tid=threadIdx.x;
    for (int i=tid;i<C1*C1;i+=blockDim.x) sw[i]=w[i];
    if (tid<C1){
        float sc=bg[tid]*rsqrtf(bv[tid]+1e-5f);
        ssc[tid]=sc; ssh[tid]=bb[tid]+(cb[tid]-bm[tid])*sc;
    }
    __syncthreads();
    int b=blockIdx.y; int t=blockIdx.x*blockDim.x+tid;
    if (t>=T0) return;
    float xv[C1];
    #pragma unroll
    for (int h=0;h<C1;h++) xv[h]=x[(b*C1+h)*T0+t];
    #pragma unroll 1
    for (int o=0;o<C1;o++){
        float acc=0.f;
        #pragma unroll
        for (int h=0;h<C1;h++) acc+=xv[h]*sw[o*C1+h];
        g_y1[(b*C1+o)*T0+t]=acc*ssc[o]+ssh[o];
    }
}

__global__ void k_conv2(const float* __restrict__ w2, const float* __restrict__ cb,
                        const float* __restrict__ bg, const float* __restrict__ bb,
                        const float* __restrict__ bm, const float* __restrict__ bv){
    __shared__ float sw[C2*C1*12];
    __shared__ float sy[C1*(TW+12)];
    __shared__ float ssc[C2], ssh[C2];
    int tid=threadIdx.x;
    for (int i=tid;i<C2*C1*12;i+=TW) sw[i]=w2[i];
    if (tid<C2){
        float sc=bg[tid]*rsqrtf(bv[tid]+1e-5f);
        ssc[tid]=sc; ssh[tid]=bb[tid]+(cb[tid]-bm[tid])*sc;
    }
    int b=blockIdx.y; int t0=blockIdx.x*TW;
    for (int i=tid;i<C1*(TW+12);i+=TW){
        int c=i/(TW+12), u=i%(TW+12);
        int tt=t0-6+u;
        sy[i]=(tt>=0 && tt<T0)? g_y1[(b*C1+c)*T0+tt] : 0.f;
    }
    __syncthreads();
    int t=t0+tid;
    if (t>=T1C) return;
    float acc[C2];
    #pragma unroll
    for (int o=0;o<C2;o++) acc[o]=0.f;
    for (int c=0;c<C1;c++){
        float yv[12];
        #pragma unroll
        for (int kk=0;kk<12;kk++) yv[kk]=sy[c*(TW+12)+tid+kk];
        #pragma unroll 1
        for (int o=0;o<C2;o++){
            float a=acc[o];
            #pragma unroll
            for (int kk=0;kk<12;kk++) a+=yv[kk]*sw[(o*C1+c)*12+kk];
            acc[o]=a;
        }
    }
    #pragma unroll 1
    for (int o=0;o<C2;o++) g_sig[(b*C2+o)*T1C+t]=acc[o]*ssc[o]+ssh[o];
}

__global__ void k_cov(){
    __shared__ float s[C2*334];
    __shared__ float cc[325];
    __shared__ float tr_s;
    int u=blockIdx.x, b=u/NEP, e=u%NEP;
    int off=e*334; int L=(e==2)?333:334;
    int tid=threadIdx.x;
    for (int idx=tid; idx<C2*L; idx+=256){
        int c=idx/L, t=idx%L;
        s[c*334+t]=g_sig[(b*C2+c)*T1C+off+t];
    }
    __syncthreads();
    if (tid<C2){
        float acc=0.f;
        for (int t=0;t<L;t++) acc+=s[tid*334+t];
        float mean=acc/(float)L;
        for (int t=0;t<L;t++) s[tid*334+t]-=mean;
    }
    __syncthreads();
    for (int r=tid;r<325;r+=256){
        int i=0, rr=r;
        while (rr>=C2-i){ rr-=C2-i; i++; }
        int j=i+rr;
        float acc=0.f;
        for (int t=0;t<L;t++) acc+=s[i*334+t]*s[j*334+t];
        cc[r]=acc/(float)(L-1);
    }
    __syncthreads();
    if (tid==0){
        float tr=0.f;
        for (int i=0;i<C2;i++) tr+=cc[i*C2 - i*(i-1)/2];
        tr_s=tr;
    }
    __syncthreads();
    float inv=1.f/tr_s;
    float* dst=g_cov+u*625;
    for (int e2=tid;e2<625;e2+=256){
        int i=e2/25, j=e2%25;
        int ii=min(i,j), jj=max(i,j);
        float v=cc[ii*C2 - ii*(ii-1)/2 + (jj-ii)]*inv;
        if (i==j) v+=1e-5f;
        dst[e2]=v;
    }
}

__global__ void k_qk(const float* __restrict__ sk0,const float* __restrict__ sk1,
                     const float* __restrict__ sk2,const float* __restrict__ sk3,
                     const float* __restrict__ sq3){
    __shared__ float scov[4][625];
    __shared__ float sK[4][31*16];
    int warp=threadIdx.x>>5, lane=threadIdx.x&31;
    int u=blockIdx.x*4+warp;
    const float* cov=g_cov+u*625;
    for (int e=lane;e<625;e+=32) scov[warp][e]=cov[e];
    __syncwarp();
    if (lane<31){
        int i=(lane==30)?29:lane;
        int k,pr,pc,gi; patch_info(i,k,pr,pc,gi);
        int kk=k*k;
        const float* W=(lane==30)? sq3 : (gi==0?sk0:gi==1?sk1:gi==2?sk2:sk3);
        float Km[16];
        #pragma unroll
        for (int e=0;e<16;e++) Km[e]=0.f;
        for (int c=0;c<kk;c++){
            int ic=(pr+c/k)*5 + pc + c%k;
            float sa[4]={0.f,0.f,0.f,0.f};
            for (int r=0;r<kk;r++){
                int ir=(pr+r/k)*5 + pc + r%k;
                float xx=scov[warp][ir*25+ic];
                #pragma unroll
                for (int a=0;a<4;a++) sa[a]+=W[r*4+a]*xx;
            }
            #pragma unroll
            for (int a=0;a<4;a++)
                #pragma unroll
                for (int b2=0;b2<4;b2++) Km[a*4+b2]+=sa[a]*W[c*4+b2];
        }
        #pragma unroll
        for (int d=0;d<4;d++) Km[d*5]+=2.5e-5f*(1.f+d);
        float logm[16];
        eigh4_log(Km, logm);
        #pragma unroll
        for (int e=0;e<16;e++) sK[warp][lane*16+e]=logm[e];
    }
    __syncwarp();
    float scval=-1e30f;
    if (lane<30){
        float kn=0.f,cr=0.f,qn=0.f;
        #pragma unroll
        for (int e=0;e<16;e++){
            float a=sK[warp][lane*16+e], q=sK[warp][30*16+e];
            kn+=a*a; cr+=a*q; qn+=q*q;
        }
        float E=fmaxf(kn+qn-2.f*cr,0.f);
        scval=1.f/(1.f+log1pf(E));
    }
    float mx=scval;
    #pragma unroll
    for (int o=16;o;o>>=1) mx=fmaxf(mx,__shfl_xor_sync(0xffffffffu,mx,o));
    float ev=(lane<30)?expf(scval-mx):0.f;
    float sm=warp_sum(ev);
    if (lane<30) g_p[u*30+lane]=ev/sm;
}

__global__ void k_logV(const float* __restrict__ sv0,const float* __restrict__ sv1,
                       const float* __restrict__ sv2,const float* __restrict__ sv3){
    __shared__ float sh[WJ][1250];
    __shared__ float scb[WJ][16], ssb[WJ][16];
    __shared__ int spq[WJ][16];
    __shared__ unsigned short sched[325];
    sched_init(sched,25);
    int warp=threadIdx.x>>5, lane=threadIdx.x&31;
    int gw=blockIdx.x*WJ+warp;
    if (gw>=NU*MM) return;
    int u=gw/MM, i=gw%MM;
    float* A=sh[warp]; float* V=A+625;
    int k,pr,pc,gi; patch_info(i,k,pr,pc,gi);
    int kk=k*k;
    const float* sv=(gi==0?sv0:gi==1?sv1:gi==2?sv2:sv3);
    const float* cov=g_cov+u*625;
    if (gi==0){
        // exact low-rank path: per-thread 4x4 eigh, near-diagonal 25x25 start
        float sm4[16], av[16], vv[16];
        #pragma unroll
        for (int e=0;e<16;e++){
            int r=e>>2, c=e&3;
            int ir=(pr+(r>>1))*5+pc+(r&1);
            int ic=(pr+(c>>1))*5+pc+(c&1);
            sm4[e]=cov[ir*25+ic]+g_E11[e];
        }
        eigh4_plain(sm4,av,vv);
        for (int e=lane;e<625;e+=32){
            int a=e/25, b=e%25;
            float val=0.f;
            if (a==b) val=(a<4)? av[a*5] : g_mu[a-4];
            else if (a<4 && b>=4){
                #pragma unroll
                for (int t=0;t<4;t++) val+=vv[t*4+a]*g_CZ[t*21+(b-4)];
            } else if (b<4 && a>=4){
                #pragma unroll
                for (int t=0;t<4;t++) val+=vv[t*4+b]*g_CZ[t*21+(a-4)];
            }
            A[e]=val;
        }
        for (int e=lane;e<625;e+=32){
            int a=e/25, j=e%25;
            float val;
            if (j<4){
                val=0.f;
                #pragma unroll
                for (int i2=0;i2<4;i2++) val+=sv0[i2*25+a]*vv[i2*4+j];
            } else val=g_P2[a*21+(j-4)];
            V[e]=val;
        }
        __syncwarp();
        warp_jacobi(A,V,25,sched,25,13,scb[warp],ssb[warp],spq[warp],true);
    } else {
        for (int e=lane;e<kk*kk;e+=32){
            int r=e/kk, c=e%kk;
            int ir=(pr+r/k)*5+pc+r%k;
            int ic=(pr+c/k)*5+pc+c%k;
            A[e]=cov[ir*25+ic];
        }
        __syncwarp();
        for (int e=lane;e<kk*25;e+=32){
            int r=e/25, b=e%25;
            float acc=0.f;
            for (int c=0;c<kk;c++) acc+=A[r*kk+c]*sv[c*25+b];
            V[e]=acc;
        }
        __syncwarp();
        for (int e=lane;e<625;e+=32){
            int a=e/25, b=e%25;
            float acc=0.f;
            for (int r=0;r<kk;r++) acc+=sv[r*25+a]*V[r*25+b];
            if (a==b) acc+=4e-6f*(1.f+a);
            A[e]=acc;
        }
        __syncwarp();
        warp_jacobi(A,V,25,sched,25,13,scb[warp],ssb[warp],spq[warp],false);
    }
    if (lane<25){ float d=A[lane*26]; A[lane*26]=logf(fmaxf(d,1e-9f)); }
    __syncwarp();
    float* out=g_V+(size_t)gw*625;
    for (int e=lane;e<625;e+=32){
        int a=e/25, b=e%25;
        float acc=0.f;
        for (int kx=0;kx<25;kx++) acc+=V[a*25+kx]*A[kx*26]*V[b*25+kx];
        out[e]=acc;
    }
}

__global__ void k_att1(){
    __shared__ float sh[WJ][1250];
    __shared__ float scb[WJ][16], ssb[WJ][16];
    __shared__ int spq[WJ][16];
    __shared__ unsigned short sched[325];
    __shared__ float pp[WJ][30];
    sched_init(sched,25);
    int warp=threadIdx.x>>5, lane=threadIdx.x&31;
    int u=blockIdx.x*WJ+warp;
    if (u>=NU) return;
    float* A=sh[warp]; float* V=A+625;
    if (lane<30) pp[warp][lane]=g_p[u*30+lane];
    __syncwarp();
    const float* Vb=g_V+(size_t)u*30*625;
    for (int e=lane;e<625;e+=32){
        float acc=0.f;
        #pragma unroll 5
        for (int i=0;i<30;i++) acc+=pp[warp][i]*Vb[(size_t)i*625+e];
        A[e]=acc;
    }
    __syncwarp();
    warp_jacobi(A,V,25,sched,25,13,scb[warp],ssb[warp],spq[warp],false);
    if (lane<25) A[lane*26]=fmaxf(expf(A[lane*26]),1e-4f);
    __syncwarp();
    float* dst=g_xm+u*625;
    for (int e=lane;e<625;e+=32){
        int a=e/25, b=e%25;
        float acc=0.f;
        for (int kx=0;kx<25;kx++) acc+=V[a*25+kx]*A[kx*26]*V[b*25+kx];
        dst[e]=acc;
    }
}

__global__ void k_s2log(const float* __restrict__ mq,const float* __restrict__ mk,
                        const float* __restrict__ mv){
    __shared__ float sh[WJ][1250];
    __shared__ float scb[WJ][16], ssb[WJ][16];
    __shared__ int spq[WJ][16];
    __shared__ unsigned short sched[153];
    sched_init(sched,18);
    int warp=threadIdx.x>>5, lane=threadIdx.x&31;
    int id=blockIdx.x*WJ+warp;
    if (id>=BB*9) return;
    int b=id/9, rem=id%9, t=rem/3, c=rem%3;
    float* A=sh[warp]; float* V=A+625;
    const float* W=(c==0?mq:(c==1?mk:mv));
    const float* X=g_xm+(b*3+t)*625;
    for (int e=lane;e<450;e+=32){
        int r=e/18, a=e%18;
        float acc=0.f;
        for (int cc=0;cc<25;cc++) acc+=X[r*25+cc]*W[cc*18+a];
        V[e]=acc;
    }
    __syncwarp();
    for (int e=lane;e<324;e+=32){
        int a=e/18, bb=e%18;
        float acc=0.f;
        for (int r=0;r<25;r++) acc+=W[r*18+a]*V[r*18+bb];
        A[e]=acc;
    }
    __syncwarp();
    warp_jacobi(A,V,18,sched,17,9,scb[warp],ssb[warp],spq[warp],false);
    if (lane<18) A[lane*19]=logf(fmaxf(A[lane*19],1e-9f));
    __syncwarp();
    float* dst=(c==0?g_logQ2:(c==1?g_logK2:g_logV2))+(b*3+t)*324;
    for (int e=lane;e<324;e+=32){
        int a=e/18, bb=e%18;
        float acc=0.f;
        for (int kx=0;kx<18;kx++) acc+=V[a*18+kx]*A[kx*19]*V[bb*18+kx];
        dst[e]=acc;
    }
}

__global__ void k_s2att(){
    __shared__ float sh[WJ][1250];
    __shared__ float scb[WJ][16], ssb[WJ][16];
    __shared__ int spq[WJ][16];
    __shared__ unsigned short sched[153];
    sched_init(sched,18);
    int warp=threadIdx.x>>5, lane=threadIdx.x&31;
    int id=blockIdx.x*WJ+warp;
    if (id>=BB*3) return;
    int b=id/3, j=id%3;
    float* A=sh[warp]; float* V=A+625;
    const float* lQ=g_logQ2+(b*3+j)*324;
    float qn=0.f;
    for (int e=lane;e<324;e+=32){ float v=lQ[e]; qn+=v*v; }
    qn=warp_sum(qn);
    float p3[3];
    #pragma unroll
    for (int i=0;i<3;i++){
        const float* lK=g_logK2+(b*3+i)*324;
        float kn=0.f, cr=0.f;
        for (int e=lane;e<324;e+=32){ float a=lK[e], q=lQ[e]; kn+=a*a; cr+=a*q; }
        kn=warp_sum(kn); cr=warp_sum(cr);
        float E=fmaxf(kn+qn-2.f*cr,0.f);
        p3[i]=1.f/(1.f+log1pf(E));
    }
    float mx=fmaxf(p3[0],fmaxf(p3[1],p3[2]));
    float sm=0.f;
    #pragma unroll
    for (int i=0;i<3;i++){ p3[i]=expf(p3[i]-mx); sm+=p3[i]; }
    #pragma unroll
    for (int i=0;i<3;i++) p3[i]/=sm;
    for (int e=lane;e<324;e+=32){
        float acc=0.f;
        #pragma unroll
        for (int i=0;i<3;i++) acc+=p3[i]*g_logV2[(b*3+i)*324+e];
        A[e]=acc;
    }
    __syncwarp();
    warp_jacobi(A,V,18,sched,17,9,scb[warp],ssb[warp],spq[warp],false);
    if (lane<18) A[lane*19]=fmaxf(A[lane*19], -9.210340371976184f);
    __syncwarp();
    for (int r=lane;r<171;r+=32){
        int ii=0, rr=r;
        while (rr>=18-ii){ rr-=18-ii; ii++; }
        int jj=ii+rr;
        float acc=0.f;
        for (int kx=0;kx<18;kx++) acc+=V[ii*18+kx]*A[kx*19]*V[jj*18+kx];
        float coef=(ii==jj)?1.f:1.41421356237309515f;
        g_feat[b*513 + j*171 + r]=acc*coef;
    }
}

__global__ void k_head(const float* __restrict__ lw, const float* __restrict__ lb,
                       float* __restrict__ out){
    int b=blockIdx.x; int o=threadIdx.x>>5; int lane=threadIdx.x&31;
    if (o>=4) return;
    float acc=0.f;
    for (int r=lane;r<513;r+=32) acc+=g_feat[b*513+r]*lw[o*513+r];
    acc=warp_sum(acc);
    if (lane==0) out[b*4+o]=acc+lb[o];
}

extern "C" void kernel_launch(void* const* d_in, const int* in_sizes, int n_in,
                              void* d_out, int out_size){
    const float* x   =(const float*)d_in[0];
    const float* c1w =(const float*)d_in[1];
    const float* c1b =(const float*)d_in[2];
    const float* bn1g=(const float*)d_in[3];
    const float* bn1b=(const float*)d_in[4];
    const float* bn1m=(const float*)d_in[5];
    const float* bn1v=(const float*)d_in[6];
    const float* c2w =(const float*)d_in[7];
    const float* c2b =(const float*)d_in[8];
    const float* bn2g=(const float*)d_in[9];
    const float* bn2b=(const float*)d_in[10];
    const float* bn2m=(const float*)d_in[11];
    const float* bn2v=(const float*)d_in[12];
    bool inter = (in_sizes[14]==16);
    const float *sk[4], *sv[4], *sq3p;
    if (inter){
        sq3p=(const float*)d_in[13+3*3];
        for (int g=0; g<4; g++){
            sk[g]=(const float*)d_in[14+3*g];
            sv[g]=(const float*)d_in[15+3*g];
        }
    } else {
        sq3p=(const float*)d_in[16];
        for (int g=0; g<4; g++){
            sk[g]=(const float*)d_in[17+g];
            sv[g]=(const float*)d_in[21+g];
        }
    }
    const float* mq=(const float*)d_in[25];
    const float* mk=(const float*)d_in[26];
    const float* mv=(const float*)d_in[27];
    const float* lw=(const float*)d_in[28];
    const float* lb=(const float*)d_in[29];

    k_prep <<<1,32>>>(sv[0]);
    k_conv1<<<dim3(8,BB),128>>>(x,c1w,c1b,bn1g,bn1b,bn1m,bn1v);
    k_conv2<<<dim3(8,BB),128>>>(c2w,c2b,bn2g,bn2b,bn2m,bn2v);
    k_cov  <<<NU,256>>>();
    k_qk   <<<NU/4,128>>>(sk[0],sk[1],sk[2],sk[3],sq3p);
    k_logV <<<(NU*MM+WJ-1)/WJ,WJ*32>>>(sv[0],sv[1],sv[2],sv[3]);
    k_att1 <<<(NU+WJ-1)/WJ,WJ*32>>>();
    k_s2log<<<(BB*9+WJ-1)/WJ,WJ*32>>>(mq,mk,mv);
    k_s2att<<<(BB*3+WJ-1)/WJ,WJ*32>>>();
    k_head <<<BB,128>>>(lw,lb,(float*)d_out);
}